// round 7
// baseline (speedup 1.0000x reference)
#include <cuda_runtime.h>
#include <cuda_fp16.h>
#include <cstdint>
#include <cstddef>

#define B_    256
#define P_    196
#define E_    2048
#define A_    512
#define MTOT  (B_*P_)      // 50176

// GEMM tiling: 128x128 tile, 256 threads, 2 CTAs/SM
#define MT 128
#define NT 128
#define KC 32
#define NKC (E_/KC)        // 64
#define NSPLIT (A_/NT)     // 4
#define STRIDE 40          // halves per smem row (80B -> conflict-free ldmatrix)

// scratch
__device__ float  g_att2[B_*A_];   // dh@Wd + Wd_b + We_b combined bias
__device__ float  g_att [MTOT];    // logits
__device__ __half g_Bth [A_*E_];   // We transposed to [N][K], fp16 (2MB)
__device__ __half g_ench[(size_t)MTOT*E_];  // enc in fp16 (side-written by GEMM, 205MB)

// ---------------- helpers ----------------
__device__ __forceinline__ void cp_async16(void* smem_dst, const void* gmem_src){
    unsigned s = (unsigned)__cvta_generic_to_shared(smem_dst);
    asm volatile("cp.async.cg.shared.global [%0], [%1], 16;\n" :: "r"(s), "l"(gmem_src));
}
__device__ __forceinline__ uint32_t packh(float a, float b){
    __half2 h = __floats2half2_rn(a, b);
    return *reinterpret_cast<uint32_t*>(&h);
}
__device__ __forceinline__ void mma_fp16(float c[4], const uint32_t a[4], uint32_t b0, uint32_t b1){
    asm volatile(
        "mma.sync.aligned.m16n8k16.row.col.f32.f16.f16.f32 "
        "{%0,%1,%2,%3}, {%4,%5,%6,%7}, {%8,%9}, {%0,%1,%2,%3};\n"
        : "+f"(c[0]), "+f"(c[1]), "+f"(c[2]), "+f"(c[3])
        : "r"(a[0]), "r"(a[1]), "r"(a[2]), "r"(a[3]), "r"(b0), "r"(b1));
}
__device__ __forceinline__ void ldsm_x4(uint32_t r[4], uint32_t saddr){
    asm volatile("ldmatrix.sync.aligned.m8n8.x4.shared.b16 {%0,%1,%2,%3}, [%4];"
        : "=r"(r[0]), "=r"(r[1]), "=r"(r[2]), "=r"(r[3]) : "r"(saddr));
}
__device__ __forceinline__ uint32_t smem_u32(const void* p){
    return (uint32_t)__cvta_generic_to_shared(p);
}

// ---------------- kernel 0: g_Bth[n][k] = fp16(We[k][n]) ----------------
__global__ void prep_bh(const float* __restrict__ We){
    __shared__ float t[32][33];
    const int k0 = blockIdx.x*32, n0 = blockIdx.y*32;
    const int tx = threadIdx.x, ty = threadIdx.y;   // (32,8)
    #pragma unroll
    for (int i = 0; i < 4; i++)
        t[ty + i*8][tx] = We[(size_t)(k0 + ty + i*8)*A_ + n0 + tx];
    __syncthreads();
    #pragma unroll
    for (int i = 0; i < 4; i++)
        g_Bth[(size_t)(n0 + ty + i*8)*E_ + k0 + tx] = __float2half_rn(t[tx][ty + i*8]);
}

// ---------------- kernel 1: att2/bias ----------------
__global__ void att2_kernel(const float* __restrict__ dh,  const float* __restrict__ Wd,
                            const float* __restrict__ Wdb, const float* __restrict__ Web){
    __shared__ float dh_s[8][512];
    const int tid = threadIdx.x;
    const int bb  = blockIdx.x * 8;
    for (int i = tid; i < 8*512; i += 128)
        dh_s[i >> 9][i & 511] = dh[(size_t)bb*512 + i];
    __syncthreads();

    float acc[8][4];
    #pragma unroll
    for (int j = 0; j < 4; j++){
        float base = Wdb[tid + j*128] + Web[tid + j*128];
        #pragma unroll
        for (int q = 0; q < 8; q++) acc[q][j] = base;
    }
    for (int k = 0; k < 512; k++){
        #pragma unroll
        for (int j = 0; j < 4; j++){
            float w = Wd[(size_t)k*512 + tid + j*128];
            #pragma unroll
            for (int q = 0; q < 8; q++) acc[q][j] += dh_s[q][k] * w;
        }
    }
    #pragma unroll
    for (int q = 0; q < 8; q++)
        #pragma unroll
        for (int j = 0; j < 4; j++)
            g_att2[(size_t)(bb+q)*512 + tid + j*128] = acc[q][j];
}

// ---------------- kernel 2: zero logits (also shifts gemm to launch idx 3 for ncu) ----
__global__ void zero_att(){
    g_att[blockIdx.x*1024 + threadIdx.x] = 0.f;     // 49 x 1024 = 50176
}

// ---------------- kernel 3: fused FP16 mma GEMM + relu + Wf-dot -> logits ----------------
// grid = 392*4 = 1568, block 256, 2 CTAs/SM.
// n0==0 CTAs also side-write enc as fp16 to g_ench (for awe).
#define STAGE_H (128*STRIDE)                         // 5120 halves
#define AS_H    (2*STAGE_H)
#define BS_H    (2*STAGE_H)
#define EX_FLOATS (256 + 128 + 128)
#define SMEM_BYTES ((AS_H + BS_H)*2 + EX_FLOATS*4)   // 43008

__global__ void __launch_bounds__(256, 2)
gemm_att_kernel(const float* __restrict__ enc, const float* __restrict__ Wf){
    extern __shared__ char smraw[];
    __half* As     = (__half*)smraw;
    __half* Bs     = As + AS_H;
    float*  bias_s = (float*)(smraw + (AS_H + BS_H)*2);   // [2][128]
    float*  wf_s   = bias_s + 256;
    float*  satt   = wf_s + 128;

    const int tid = threadIdx.x;
    const int bid = blockIdx.x;
    const int m0  = (bid >> 2) * MT;
    const int n0  = (bid & 3)  * NT;
    const int b_first = m0 / P_;
    const bool side_write = (n0 == 0);

    {
        int j = tid >> 7, c2 = tid & 127;                 // 2 x 128
        int b = b_first + j;
        bias_s[tid] = (b < B_) ? g_att2[(size_t)b*A_ + n0 + c2] : 0.f;
        if (tid < 128){ wf_s[tid] = Wf[n0 + tid]; satt[tid] = 0.f; }
    }

    const int warp = tid >> 5, lane = tid & 31;
    const int wm = warp >> 1, wn = warp & 1;        // 4x2 warp grid; warp tile 32x64
    const int g = lane >> 2, t = lane & 3;

    const uint32_t as_base = smem_u32(As);
    const uint32_t bs_base = smem_u32(Bs);

    // ldmatrix lane addressing (halves)
    const int a_row  = lane & 15;
    const int a_koff = (lane >> 4) * 8;
    const int b_row  = (lane & 7) + ((lane >> 4) & 1) * 8;
    const int b_koff = ((lane >> 3) & 1) * 8;

    // A staging: thread covers row = tid>>1 (all 128 rows), kseg = tid&1 (16 floats)
    const int st_row  = tid >> 1;
    const int st_kseg = tid & 1;
    const float4* Ag = (const float4*)(enc + (size_t)(m0 + st_row)*E_) + st_kseg*4;
    __half* AsW = As + st_row*STRIDE + st_kseg*16;
    uint32_t* ench32 = (uint32_t*)(g_ench + (size_t)(m0 + st_row)*E_) + st_kseg*8;

    // B staging via cp.async
    const __half* Bg = g_Bth + (size_t)n0*E_;

    float c[2][8][4];
    #pragma unroll
    for (int mi = 0; mi < 2; mi++)
        #pragma unroll
        for (int ni = 0; ni < 8; ni++)
            #pragma unroll
            for (int j = 0; j < 4; j++) c[mi][ni][j] = 0.f;

    // ---- prologue: stage chunk 0 ----
    {
        float4 v[4];
        #pragma unroll
        for (int j = 0; j < 4; j++) v[j] = Ag[j];          // kc=0
        uint32_t w[8];
        #pragma unroll
        for (int j = 0; j < 4; j++){
            w[j*2+0] = packh(v[j].x, v[j].y);
            w[j*2+1] = packh(v[j].z, v[j].w);
        }
        uint32_t* ws = (uint32_t*)AsW;
        #pragma unroll
        for (int j = 0; j < 8; j++) ws[j] = w[j];
        if (side_write){
            ((uint4*)ench32)[0] = make_uint4(w[0], w[1], w[2], w[3]);
            ((uint4*)ench32)[1] = make_uint4(w[4], w[5], w[6], w[7]);
        }
        #pragma unroll
        for (int i = 0; i < 2; i++){
            int idx = tid + i*256;
            int n = idx >> 2, seg = idx & 3;
            cp_async16(Bs + n*STRIDE + seg*8, Bg + (size_t)n*E_ + seg*8);
        }
        asm volatile("cp.async.commit_group;\n");
    }

    for (int kc = 0; kc < NKC; kc++){
        const int buf = kc & 1;
        const uint32_t a_cta = as_base + (uint32_t)buf*STAGE_H*2;
        const uint32_t b_cta = bs_base + (uint32_t)buf*STAGE_H*2;
        __half* AsN = As + (buf^1)*STAGE_H;
        __half* BsN = Bs + (buf^1)*STAGE_H;

        float4 v[4];
        const bool pref = (kc + 1 < NKC);
        if (pref){
            // B chunk kc+1
            #pragma unroll
            for (int i = 0; i < 2; i++){
                int idx = tid + i*256;
                int n = idx >> 2, seg = idx & 3;
                cp_async16(BsN + n*STRIDE + seg*8, Bg + (size_t)n*E_ + (kc+1)*KC + seg*8);
            }
            asm volatile("cp.async.commit_group;\n");
            // A chunk kc+1 -> regs (covers ALL 128 rows: 2 threads per row)
            #pragma unroll
            for (int j = 0; j < 4; j++) v[j] = Ag[(size_t)(kc+1)*(KC/4) + j];
        }

        if (pref) asm volatile("cp.async.wait_group 1;\n");
        else      asm volatile("cp.async.wait_group 0;\n");
        __syncthreads();

        // fragment base addresses (bytes)
        const uint32_t a_base = a_cta + (uint32_t)(((wm*32 + a_row)*STRIDE + a_koff) * 2);
        const uint32_t b_base = b_cta + (uint32_t)(((wn*64 + b_row)*STRIDE + b_koff) * 2);

        #pragma unroll
        for (int ks = 0; ks < 2; ks++){
            uint32_t a[2][4], b[4][4];
            #pragma unroll
            for (int mi = 0; mi < 2; mi++)
                ldsm_x4(a[mi], a_base + (uint32_t)((mi*16*STRIDE + ks*16) * 2));
            #pragma unroll
            for (int p = 0; p < 4; p++)
                ldsm_x4(b[p], b_base + (uint32_t)((p*16*STRIDE + ks*16) * 2));
            #pragma unroll
            for (int p = 0; p < 4; p++){
                mma_fp16(c[0][2*p+0], a[0], b[p][0], b[p][1]);
                mma_fp16(c[1][2*p+0], a[1], b[p][0], b[p][1]);
                mma_fp16(c[0][2*p+1], a[0], b[p][2], b[p][3]);
                mma_fp16(c[1][2*p+1], a[1], b[p][2], b[p][3]);
            }
        }

        if (pref){
            // convert + store A chunk kc+1 into buf^1 (+ optional fp16 side-write)
            uint32_t w[8];
            #pragma unroll
            for (int j = 0; j < 4; j++){
                w[j*2+0] = packh(v[j].x, v[j].y);
                w[j*2+1] = packh(v[j].z, v[j].w);
            }
            uint32_t* ws = (uint32_t*)(AsN + st_row*STRIDE + st_kseg*16);
            #pragma unroll
            for (int j = 0; j < 8; j++) ws[j] = w[j];
            if (side_write){
                uint4* d = (uint4*)(ench32 + (size_t)(kc+1)*16);
                d[0] = make_uint4(w[0], w[1], w[2], w[3]);
                d[1] = make_uint4(w[4], w[5], w[6], w[7]);
            }
        }
        __syncthreads();
    }

    // epilogue: h = relu(acc + bias(b_row, col)); att += h .* Wf
    float attr[2][2] = {{0.f,0.f},{0.f,0.f}};
    #pragma unroll
    for (int ni = 0; ni < 8; ni++){
        const int cl = wn*64 + ni*8 + 2*t;               // local col
        const float w0 = wf_s[cl], w1 = wf_s[cl+1];
        #pragma unroll
        for (int mi = 0; mi < 2; mi++){
            #pragma unroll
            for (int rr = 0; rr < 2; rr++){
                const int rowg = m0 + wm*32 + mi*16 + g + rr*8;
                const int rb   = rowg / P_ - b_first;          // 0 or 1
                const float bv0 = bias_s[rb*128 + cl];
                const float bv1 = bias_s[rb*128 + cl + 1];
                const float h0 = fmaxf(c[mi][ni][rr*2+0] + bv0, 0.f);
                const float h1 = fmaxf(c[mi][ni][rr*2+1] + bv1, 0.f);
                attr[mi][rr] += h0*w0 + h1*w1;
            }
        }
    }
    #pragma unroll
    for (int mi = 0; mi < 2; mi++)
        #pragma unroll
        for (int rr = 0; rr < 2; rr++){
            float v = attr[mi][rr];
            v += __shfl_xor_sync(0xffffffffu, v, 1);
            v += __shfl_xor_sync(0xffffffffu, v, 2);
            if (t == 0) atomicAdd(&satt[wm*32 + mi*16 + g + rr*8], v);
        }
    __syncthreads();
    if (tid < 128) atomicAdd(&g_att[m0 + tid], satt[tid]);
}

// ---------------- kernel 4: softmax over P per batch row ----------------
__global__ void softmax_kernel(float* __restrict__ alpha_out){
    const int b = blockIdx.x, tid = threadIdx.x;    // 256 threads
    __shared__ float red[256];
    float v = (tid < P_) ? g_att[b*P_ + tid] : -1e30f;
    red[tid] = v; __syncthreads();
    for (int s = 128; s > 0; s >>= 1){
        if (tid < s) red[tid] = fmaxf(red[tid], red[tid+s]);
        __syncthreads();
    }
    const float mx = red[0]; __syncthreads();
    const float e = (tid < P_) ? expf(v - mx) : 0.f;
    red[tid] = e; __syncthreads();
    for (int s = 128; s > 0; s >>= 1){
        if (tid < s) red[tid] += red[tid+s];
        __syncthreads();
    }
    const float inv = 1.f / red[0];
    if (tid < P_) alpha_out[b*P_ + tid] = e * inv;
}

// ---------------- kernel 5: awe[b,e] = sum_p ench[b,p,e] * alpha[b,p] (fp16 enc) --------
__global__ void __launch_bounds__(512)
awe_kernel(const float* __restrict__ alpha, float4* __restrict__ out4){
    const int b = blockIdx.x, tid = threadIdx.x;    // 512 threads, 4 halves each
    __shared__ float al[P_];
    if (tid < P_) al[tid] = alpha[b*P_ + tid];
    __syncthreads();
    float4 acc = make_float4(0.f, 0.f, 0.f, 0.f);
    const uint2* ep = (const uint2*)(g_ench + (size_t)b * P_ * E_) + tid;
    #pragma unroll 4
    for (int p = 0; p < P_; p++){
        const float a = al[p];
        const uint2 u = ep[(size_t)p * (E_/4)];
        const __half2 h0 = *(const __half2*)&u.x;
        const __half2 h1 = *(const __half2*)&u.y;
        acc.x += a * __low2float(h0);  acc.y += a * __high2float(h0);
        acc.z += a * __low2float(h1);  acc.w += a * __high2float(h1);
    }
    out4[(size_t)b * (E_/4) + tid] = acc;
}

// ---------------- launch ----------------
extern "C" void kernel_launch(void* const* d_in, const int* in_sizes, int n_in,
                              void* d_out, int out_size){
    const float* enc  = (const float*)d_in[0];   // (B,P,E)
    const float* dh   = (const float*)d_in[1];   // (1,B,D)
    const float* We_w = (const float*)d_in[2];   // (E,A)
    const float* We_b = (const float*)d_in[3];   // (A)
    const float* Wd_w = (const float*)d_in[4];   // (D,A)
    const float* Wd_b = (const float*)d_in[5];   // (A)
    const float* Wf_w = (const float*)d_in[6];   // (A)
    // d_in[7] = Wf_b: scalar logit shift -> softmax-invariant, outputs don't depend on it.

    float* out       = (float*)d_out;
    float* awe_out   = out;                       // (B,E)
    float* alpha_out = out + (size_t)B_*E_;       // (B,P)

    cudaFuncSetAttribute(gemm_att_kernel, cudaFuncAttributeMaxDynamicSharedMemorySize, SMEM_BYTES);

    prep_bh       <<<dim3(E_/32, A_/32), dim3(32, 8)>>>(We_w);
    att2_kernel   <<<32, 128>>>(dh, Wd_w, Wd_b, We_b);
    zero_att      <<<MTOT/1024, 1024>>>();
    gemm_att_kernel<<<(MTOT/MT)*NSPLIT, 256, SMEM_BYTES>>>(enc, Wf_w);   // launch idx 3 -> ncu target
    softmax_kernel<<<B_, 256>>>(alpha_out);
    awe_kernel    <<<B_, 512>>>(alpha_out, (float4*)awe_out);
}

// round 8
// speedup vs baseline: 1.0650x; 1.0650x over previous
#include <cuda_runtime.h>
#include <cuda_fp16.h>
#include <cstdint>
#include <cstddef>

#define B_    256
#define P_    196
#define E_    2048
#define A_    512
#define MTOT  (B_*P_)      // 50176

// GEMM tiling: 128x128 tile, 256 threads, 2 CTAs/SM
#define MT 128
#define NT 128
#define KC 32
#define NKC (E_/KC)        // 64
#define NSPLIT (A_/NT)     // 4
#define STRIDE 40          // halves per smem row (80B -> conflict-free ldmatrix)

// scratch
__device__ float  g_att2[B_*A_];   // dh@Wd + Wd_b + We_b combined bias
__device__ float  g_att [MTOT];    // logits
__device__ __half g_Bth [A_*E_];   // We transposed to [N][K], fp16 (2MB)
__device__ __half g_ench[(size_t)MTOT*E_];  // enc in fp16 (205MB)

// ---------------- helpers ----------------
__device__ __forceinline__ void cp_async16(void* smem_dst, const void* gmem_src){
    unsigned s = (unsigned)__cvta_generic_to_shared(smem_dst);
    asm volatile("cp.async.cg.shared.global [%0], [%1], 16;\n" :: "r"(s), "l"(gmem_src));
}
__device__ __forceinline__ uint32_t packh(float a, float b){
    __half2 h = __floats2half2_rn(a, b);
    return *reinterpret_cast<uint32_t*>(&h);
}
__device__ __forceinline__ void mma_fp16(float c[4], const uint32_t a[4], uint32_t b0, uint32_t b1){
    asm volatile(
        "mma.sync.aligned.m16n8k16.row.col.f32.f16.f16.f32 "
        "{%0,%1,%2,%3}, {%4,%5,%6,%7}, {%8,%9}, {%0,%1,%2,%3};\n"
        : "+f"(c[0]), "+f"(c[1]), "+f"(c[2]), "+f"(c[3])
        : "r"(a[0]), "r"(a[1]), "r"(a[2]), "r"(a[3]), "r"(b0), "r"(b1));
}
__device__ __forceinline__ void ldsm_x4(uint32_t r[4], uint32_t saddr){
    asm volatile("ldmatrix.sync.aligned.m8n8.x4.shared.b16 {%0,%1,%2,%3}, [%4];"
        : "=r"(r[0]), "=r"(r[1]), "=r"(r[2]), "=r"(r[3]) : "r"(saddr));
}
__device__ __forceinline__ uint32_t smem_u32(const void* p){
    return (uint32_t)__cvta_generic_to_shared(p);
}

// ---------------- kernel 0: g_Bth[n][k] = fp16(We[k][n]) ----------------
__global__ void prep_bh(const float* __restrict__ We){
    __shared__ float t[32][33];
    const int k0 = blockIdx.x*32, n0 = blockIdx.y*32;
    const int tx = threadIdx.x, ty = threadIdx.y;   // (32,8)
    #pragma unroll
    for (int i = 0; i < 4; i++)
        t[ty + i*8][tx] = We[(size_t)(k0 + ty + i*8)*A_ + n0 + tx];
    __syncthreads();
    #pragma unroll
    for (int i = 0; i < 4; i++)
        g_Bth[(size_t)(n0 + ty + i*8)*E_ + k0 + tx] = __float2half_rn(t[tx][ty + i*8]);
}

// ---------------- kernel 1: enc -> fp16 (streaming) + zero logits ----------------
// grid = MTOT*E/(512*8) = 25088 blocks, 512 threads, 8 floats each.
__global__ void __launch_bounds__(512)
prep_ench(const float* __restrict__ enc){
    const size_t i = ((size_t)blockIdx.x*512 + threadIdx.x)*8;
    const float4 v0 = *(const float4*)(enc + i);
    const float4 v1 = *(const float4*)(enc + i + 4);
    uint4 w;
    w.x = packh(v0.x, v0.y);  w.y = packh(v0.z, v0.w);
    w.z = packh(v1.x, v1.y);  w.w = packh(v1.z, v1.w);
    *(uint4*)(g_ench + i) = w;
    const int j = blockIdx.x*512 + threadIdx.x;
    if (j < MTOT) g_att[j] = 0.f;
}

// ---------------- kernel 2: att2/bias ----------------
__global__ void att2_kernel(const float* __restrict__ dh,  const float* __restrict__ Wd,
                            const float* __restrict__ Wdb, const float* __restrict__ Web){
    __shared__ float dh_s[8][512];
    const int tid = threadIdx.x;
    const int bb  = blockIdx.x * 8;
    for (int i = tid; i < 8*512; i += 128)
        dh_s[i >> 9][i & 511] = dh[(size_t)bb*512 + i];
    __syncthreads();

    float acc[8][4];
    #pragma unroll
    for (int j = 0; j < 4; j++){
        float base = Wdb[tid + j*128] + Web[tid + j*128];
        #pragma unroll
        for (int q = 0; q < 8; q++) acc[q][j] = base;
    }
    for (int k = 0; k < 512; k++){
        #pragma unroll
        for (int j = 0; j < 4; j++){
            float w = Wd[(size_t)k*512 + tid + j*128];
            #pragma unroll
            for (int q = 0; q < 8; q++) acc[q][j] += dh_s[q][k] * w;
        }
    }
    #pragma unroll
    for (int q = 0; q < 8; q++)
        #pragma unroll
        for (int j = 0; j < 4; j++)
            g_att2[(size_t)(bb+q)*512 + tid + j*128] = acc[q][j];
}

// ---------------- kernel 3 (ncu launch idx 3): fp16 GEMM + relu + Wf-dot -> logits ----
// grid = 392*4 = 1568, block 256, 2 CTAs/SM. Pure cp.async + LDSM + HMMA inner loop.
#define STAGE_H (128*STRIDE)                         // 5120 halves
#define AS_H    (2*STAGE_H)
#define BS_H    (2*STAGE_H)
#define EX_FLOATS (256 + 128 + 128)
#define SMEM_BYTES ((AS_H + BS_H)*2 + EX_FLOATS*4)   // 43008

__global__ void __launch_bounds__(256, 2)
gemm_att_kernel(const float* __restrict__ Wf){
    extern __shared__ char smraw[];
    __half* As     = (__half*)smraw;
    __half* Bs     = As + AS_H;
    float*  bias_s = (float*)(smraw + (AS_H + BS_H)*2);   // [2][128]
    float*  wf_s   = bias_s + 256;
    float*  satt   = wf_s + 128;

    const int tid = threadIdx.x;
    const int bid = blockIdx.x;
    const int m0  = (bid >> 2) * MT;
    const int n0  = (bid & 3)  * NT;
    const int b_first = m0 / P_;

    {
        int j = tid >> 7, c2 = tid & 127;                 // 2 x 128
        int b = b_first + j;
        bias_s[tid] = (b < B_) ? g_att2[(size_t)b*A_ + n0 + c2] : 0.f;
        if (tid < 128){ wf_s[tid] = Wf[n0 + tid]; satt[tid] = 0.f; }
    }

    const int warp = tid >> 5, lane = tid & 31;
    const int wm = warp >> 1, wn = warp & 1;        // 4x2 warp grid; warp tile 32x64
    const int g = lane >> 2, t = lane & 3;

    const uint32_t as_base = smem_u32(As);
    const uint32_t bs_base = smem_u32(Bs);

    // ldmatrix lane addressing (halves)
    const int a_row  = lane & 15;
    const int a_koff = (lane >> 4) * 8;
    const int b_row  = (lane & 7) + ((lane >> 4) & 1) * 8;
    const int b_koff = ((lane >> 3) & 1) * 8;

    // staging addressing: 512 16B-chunks per tile; thread covers 2 (A) + 2 (B)
    const int ld_row = tid >> 1;                    // rows 0..127, 2 threads/row
    const int ld_sg  = (tid & 1) * 2;               // seg 0/1 or 2/3
    const __half* Agl = g_ench + (size_t)(m0 + ld_row)*E_ + ld_sg*8;
    const __half* Bgl = g_Bth  + (size_t)(n0 + ld_row)*E_ + ld_sg*8;
    __half* AsW = As + ld_row*STRIDE + ld_sg*8;
    __half* BsW = Bs + ld_row*STRIDE + ld_sg*8;

    float c[2][8][4];
    #pragma unroll
    for (int mi = 0; mi < 2; mi++)
        #pragma unroll
        for (int ni = 0; ni < 8; ni++)
            #pragma unroll
            for (int j = 0; j < 4; j++) c[mi][ni][j] = 0.f;

    // ---- prologue: stage chunk 0 into buf 0 ----
    cp_async16(AsW,     Agl);
    cp_async16(AsW + 8, Agl + 8);
    cp_async16(BsW,     Bgl);
    cp_async16(BsW + 8, Bgl + 8);
    asm volatile("cp.async.commit_group;\n");

    for (int kc = 0; kc < NKC; kc++){
        const int buf = kc & 1;
        const uint32_t a_cta = as_base + (uint32_t)buf*STAGE_H*2;
        const uint32_t b_cta = bs_base + (uint32_t)buf*STAGE_H*2;

        const bool pref = (kc + 1 < NKC);
        if (pref){
            const int nb = buf ^ 1;
            const size_t ko = (size_t)(kc+1)*KC;
            cp_async16(AsW + nb*STAGE_H,     Agl + ko);
            cp_async16(AsW + nb*STAGE_H + 8, Agl + ko + 8);
            cp_async16(BsW + nb*STAGE_H,     Bgl + ko);
            cp_async16(BsW + nb*STAGE_H + 8, Bgl + ko + 8);
            asm volatile("cp.async.commit_group;\n");
            asm volatile("cp.async.wait_group 1;\n");
        } else {
            asm volatile("cp.async.wait_group 0;\n");
        }
        __syncthreads();

        const uint32_t a_base = a_cta + (uint32_t)(((wm*32 + a_row)*STRIDE + a_koff) * 2);
        const uint32_t b_base = b_cta + (uint32_t)(((wn*64 + b_row)*STRIDE + b_koff) * 2);

        #pragma unroll
        for (int ks = 0; ks < 2; ks++){
            uint32_t a[2][4], b[4][4];
            #pragma unroll
            for (int mi = 0; mi < 2; mi++)
                ldsm_x4(a[mi], a_base + (uint32_t)((mi*16*STRIDE + ks*16) * 2));
            #pragma unroll
            for (int p = 0; p < 4; p++)
                ldsm_x4(b[p], b_base + (uint32_t)((p*16*STRIDE + ks*16) * 2));
            #pragma unroll
            for (int p = 0; p < 4; p++){
                mma_fp16(c[0][2*p+0], a[0], b[p][0], b[p][1]);
                mma_fp16(c[1][2*p+0], a[1], b[p][0], b[p][1]);
                mma_fp16(c[0][2*p+1], a[0], b[p][2], b[p][3]);
                mma_fp16(c[1][2*p+1], a[1], b[p][2], b[p][3]);
            }
        }
        __syncthreads();
    }

    // epilogue: h = relu(acc + bias(b_row, col)); att += h .* Wf
    float attr[2][2] = {{0.f,0.f},{0.f,0.f}};
    #pragma unroll
    for (int ni = 0; ni < 8; ni++){
        const int cl = wn*64 + ni*8 + 2*t;               // local col
        const float w0 = wf_s[cl], w1 = wf_s[cl+1];
        #pragma unroll
        for (int mi = 0; mi < 2; mi++){
            #pragma unroll
            for (int rr = 0; rr < 2; rr++){
                const int rowg = m0 + wm*32 + mi*16 + g + rr*8;
                const int rb   = rowg / P_ - b_first;          // 0 or 1
                const float bv0 = bias_s[rb*128 + cl];
                const float bv1 = bias_s[rb*128 + cl + 1];
                const float h0 = fmaxf(c[mi][ni][rr*2+0] + bv0, 0.f);
                const float h1 = fmaxf(c[mi][ni][rr*2+1] + bv1, 0.f);
                attr[mi][rr] += h0*w0 + h1*w1;
            }
        }
    }
    #pragma unroll
    for (int mi = 0; mi < 2; mi++)
        #pragma unroll
        for (int rr = 0; rr < 2; rr++){
            float v = attr[mi][rr];
            v += __shfl_xor_sync(0xffffffffu, v, 1);
            v += __shfl_xor_sync(0xffffffffu, v, 2);
            if (t == 0) atomicAdd(&satt[wm*32 + mi*16 + g + rr*8], v);
        }
    __syncthreads();
    if (tid < 128) atomicAdd(&g_att[m0 + tid], satt[tid]);
}

// ---------------- kernel 4: softmax over P per batch row ----------------
__global__ void softmax_kernel(float* __restrict__ alpha_out){
    const int b = blockIdx.x, tid = threadIdx.x;    // 256 threads
    __shared__ float red[256];
    float v = (tid < P_) ? g_att[b*P_ + tid] : -1e30f;
    red[tid] = v; __syncthreads();
    for (int s = 128; s > 0; s >>= 1){
        if (tid < s) red[tid] = fmaxf(red[tid], red[tid+s]);
        __syncthreads();
    }
    const float mx = red[0]; __syncthreads();
    const float e = (tid < P_) ? expf(v - mx) : 0.f;
    red[tid] = e; __syncthreads();
    for (int s = 128; s > 0; s >>= 1){
        if (tid < s) red[tid] += red[tid+s];
        __syncthreads();
    }
    const float inv = 1.f / red[0];
    if (tid < P_) alpha_out[b*P_ + tid] = e * inv;
}

// ---------------- kernel 5: awe[b,e] = sum_p ench[b,p,e] * alpha[b,p] (fp16 enc) --------
__global__ void __launch_bounds__(512)
awe_kernel(const float* __restrict__ alpha, float4* __restrict__ out4){
    const int b = blockIdx.x, tid = threadIdx.x;    // 512 threads, 4 halves each
    __shared__ float al[P_];
    if (tid < P_) al[tid] = alpha[b*P_ + tid];
    __syncthreads();
    float4 acc = make_float4(0.f, 0.f, 0.f, 0.f);
    const uint2* ep = (const uint2*)(g_ench + (size_t)b * P_ * E_) + tid;
    #pragma unroll 4
    for (int p = 0; p < P_; p++){
        const float a = al[p];
        const uint2 u = ep[(size_t)p * (E_/4)];
        const __half2 h0 = *(const __half2*)&u.x;
        const __half2 h1 = *(const __half2*)&u.y;
        acc.x += a * __low2float(h0);  acc.y += a * __high2float(h0);
        acc.z += a * __low2float(h1);  acc.w += a * __high2float(h1);
    }
    out4[(size_t)b * (E_/4) + tid] = acc;
}

// ---------------- launch ----------------
extern "C" void kernel_launch(void* const* d_in, const int* in_sizes, int n_in,
                              void* d_out, int out_size){
    const float* enc  = (const float*)d_in[0];   // (B,P,E)
    const float* dh   = (const float*)d_in[1];   // (1,B,D)
    const float* We_w = (const float*)d_in[2];   // (E,A)
    const float* We_b = (const float*)d_in[3];   // (A)
    const float* Wd_w = (const float*)d_in[4];   // (D,A)
    const float* Wd_b = (const float*)d_in[5];   // (A)
    const float* Wf_w = (const float*)d_in[6];   // (A)
    // d_in[7] = Wf_b: scalar logit shift -> softmax-invariant, outputs don't depend on it.

    float* out       = (float*)d_out;
    float* awe_out   = out;                       // (B,E)
    float* alpha_out = out + (size_t)B_*E_;       // (B,P)

    cudaFuncSetAttribute(gemm_att_kernel, cudaFuncAttributeMaxDynamicSharedMemorySize, SMEM_BYTES);

    prep_bh       <<<dim3(E_/32, A_/32), dim3(32, 8)>>>(We_w);
    prep_ench     <<<(int)((size_t)MTOT*E_/(512*8)), 512>>>(enc);
    att2_kernel   <<<32, 128>>>(dh, Wd_w, Wd_b, We_b);
    gemm_att_kernel<<<(MTOT/MT)*NSPLIT, 256, SMEM_BYTES>>>(Wf_w);   // launch idx 3 -> ncu target
    softmax_kernel<<<B_, 256>>>(alpha_out);
    awe_kernel    <<<B_, 512>>>(alpha_out, (float4*)awe_out);
}

// round 9
// speedup vs baseline: 1.0930x; 1.0263x over previous
#include <cuda_runtime.h>
#include <cuda_fp16.h>
#include <cstdint>
#include <cstddef>

#define B_    256
#define P_    196
#define E_    2048
#define A_    512
#define MTOT  (B_*P_)      // 50176

// GEMM tiling: 128x128 tile, 256 threads, 2 CTAs/SM, 4-stage cp.async ring
#define MT 128
#define NT 128
#define KC 32
#define NKC (E_/KC)        // 64
#define NSPLIT (A_/NT)     // 4
#define STRIDE 40          // halves per smem row (80B -> conflict-free ldmatrix)
#define NSTAGE 4

// scratch
__device__ float  g_att2[B_*A_];   // dh@Wd + Wd_b + We_b combined bias
__device__ float  g_att [MTOT];    // logits
__device__ __half g_Bth [A_*E_];   // We transposed to [N][K], fp16 (2MB)
__device__ __half g_ench[(size_t)MTOT*E_];  // enc in fp16 (205MB)

// ---------------- helpers ----------------
__device__ __forceinline__ void cp_async16(void* smem_dst, const void* gmem_src){
    unsigned s = (unsigned)__cvta_generic_to_shared(smem_dst);
    asm volatile("cp.async.cg.shared.global [%0], [%1], 16;\n" :: "r"(s), "l"(gmem_src));
}
__device__ __forceinline__ uint32_t packh(float a, float b){
    __half2 h = __floats2half2_rn(a, b);
    return *reinterpret_cast<uint32_t*>(&h);
}
__device__ __forceinline__ void mma_fp16(float c[4], const uint32_t a[4], uint32_t b0, uint32_t b1){
    asm volatile(
        "mma.sync.aligned.m16n8k16.row.col.f32.f16.f16.f32 "
        "{%0,%1,%2,%3}, {%4,%5,%6,%7}, {%8,%9}, {%0,%1,%2,%3};\n"
        : "+f"(c[0]), "+f"(c[1]), "+f"(c[2]), "+f"(c[3])
        : "r"(a[0]), "r"(a[1]), "r"(a[2]), "r"(a[3]), "r"(b0), "r"(b1));
}
__device__ __forceinline__ void ldsm_x4(uint32_t r[4], uint32_t saddr){
    asm volatile("ldmatrix.sync.aligned.m8n8.x4.shared.b16 {%0,%1,%2,%3}, [%4];"
        : "=r"(r[0]), "=r"(r[1]), "=r"(r[2]), "=r"(r[3]) : "r"(saddr));
}
__device__ __forceinline__ uint32_t smem_u32(const void* p){
    return (uint32_t)__cvta_generic_to_shared(p);
}

// ---------------- kernel 0: g_Bth[n][k] = fp16(We[k][n]) ----------------
__global__ void prep_bh(const float* __restrict__ We){
    __shared__ float t[32][33];
    const int k0 = blockIdx.x*32, n0 = blockIdx.y*32;
    const int tx = threadIdx.x, ty = threadIdx.y;   // (32,8)
    #pragma unroll
    for (int i = 0; i < 4; i++)
        t[ty + i*8][tx] = We[(size_t)(k0 + ty + i*8)*A_ + n0 + tx];
    __syncthreads();
    #pragma unroll
    for (int i = 0; i < 4; i++)
        g_Bth[(size_t)(n0 + ty + i*8)*E_ + k0 + tx] = __float2half_rn(t[tx][ty + i*8]);
}

// ---------------- kernel 1: enc -> fp16 (streaming) + zero logits ----------------
__global__ void __launch_bounds__(512)
prep_ench(const float* __restrict__ enc){
    const size_t i = ((size_t)blockIdx.x*512 + threadIdx.x)*8;
    const float4 v0 = *(const float4*)(enc + i);
    const float4 v1 = *(const float4*)(enc + i + 4);
    uint4 w;
    w.x = packh(v0.x, v0.y);  w.y = packh(v0.z, v0.w);
    w.z = packh(v1.x, v1.y);  w.w = packh(v1.z, v1.w);
    *(uint4*)(g_ench + i) = w;
    const int j = blockIdx.x*512 + threadIdx.x;
    if (j < MTOT) g_att[j] = 0.f;
}

// ---------------- kernel 2: att2/bias ----------------
__global__ void att2_kernel(const float* __restrict__ dh,  const float* __restrict__ Wd,
                            const float* __restrict__ Wdb, const float* __restrict__ Web){
    __shared__ float dh_s[8][512];
    const int tid = threadIdx.x;
    const int bb  = blockIdx.x * 8;
    for (int i = tid; i < 8*512; i += 128)
        dh_s[i >> 9][i & 511] = dh[(size_t)bb*512 + i];
    __syncthreads();

    float acc[8][4];
    #pragma unroll
    for (int j = 0; j < 4; j++){
        float base = Wdb[tid + j*128] + Web[tid + j*128];
        #pragma unroll
        for (int q = 0; q < 8; q++) acc[q][j] = base;
    }
    for (int k = 0; k < 512; k++){
        #pragma unroll
        for (int j = 0; j < 4; j++){
            float w = Wd[(size_t)k*512 + tid + j*128];
            #pragma unroll
            for (int q = 0; q < 8; q++) acc[q][j] += dh_s[q][k] * w;
        }
    }
    #pragma unroll
    for (int q = 0; q < 8; q++)
        #pragma unroll
        for (int j = 0; j < 4; j++)
            g_att2[(size_t)(bb+q)*512 + tid + j*128] = acc[q][j];
}

// ---------------- kernel 3 (ncu idx 3): fp16 GEMM, 4-stage ring, 1 sync/chunk ----------
#define STAGE_H (128*STRIDE)                         // 5120 halves = 10KB
#define AS_H    (NSTAGE*STAGE_H)
#define BS_H    (NSTAGE*STAGE_H)
#define EX_FLOATS (256 + 128 + 128)
#define SMEM_BYTES ((AS_H + BS_H)*2 + EX_FLOATS*4)   // 83968

__global__ void __launch_bounds__(256, 2)
gemm_att_kernel(const float* __restrict__ Wf){
    extern __shared__ char smraw[];
    __half* As     = (__half*)smraw;
    __half* Bs     = As + AS_H;
    float*  bias_s = (float*)(smraw + (AS_H + BS_H)*2);   // [2][128]
    float*  wf_s   = bias_s + 256;
    float*  satt   = wf_s + 128;

    const int tid = threadIdx.x;
    const int bid = blockIdx.x;
    const int m0  = (bid >> 2) * MT;
    const int n0  = (bid & 3)  * NT;
    const int b_first = m0 / P_;

    {
        int j = tid >> 7, c2 = tid & 127;                 // 2 x 128
        int b = b_first + j;
        bias_s[tid] = (b < B_) ? g_att2[(size_t)b*A_ + n0 + c2] : 0.f;
        if (tid < 128){ wf_s[tid] = Wf[n0 + tid]; satt[tid] = 0.f; }
    }

    const int warp = tid >> 5, lane = tid & 31;
    const int wm = warp >> 1, wn = warp & 1;        // 4x2 warp grid; warp tile 32x64
    const int g = lane >> 2, t = lane & 3;

    const uint32_t as_base = smem_u32(As);
    const uint32_t bs_base = smem_u32(Bs);

    // ldmatrix lane addressing (halves)
    const int a_row  = lane & 15;
    const int a_koff = (lane >> 4) * 8;
    const int b_row  = (lane & 7) + ((lane >> 4) & 1) * 8;
    const int b_koff = ((lane >> 3) & 1) * 8;

    // staging addressing: thread covers 2x16B (A) + 2x16B (B) per chunk
    const int ld_row = tid >> 1;
    const int ld_sg  = (tid & 1) * 2;
    const __half* Agl = g_ench + (size_t)(m0 + ld_row)*E_ + ld_sg*8;
    const __half* Bgl = g_Bth  + (size_t)(n0 + ld_row)*E_ + ld_sg*8;
    __half* AsW = As + ld_row*STRIDE + ld_sg*8;
    __half* BsW = Bs + ld_row*STRIDE + ld_sg*8;

    float c[2][8][4];
    #pragma unroll
    for (int mi = 0; mi < 2; mi++)
        #pragma unroll
        for (int ni = 0; ni < 8; ni++)
            #pragma unroll
            for (int j = 0; j < 4; j++) c[mi][ni][j] = 0.f;

    // ---- prologue: stage chunks 0..2 into stages 0..2 ----
    #pragma unroll
    for (int s = 0; s < 3; s++){
        const size_t ko = (size_t)s*KC;
        cp_async16(AsW + s*STAGE_H,     Agl + ko);
        cp_async16(AsW + s*STAGE_H + 8, Agl + ko + 8);
        cp_async16(BsW + s*STAGE_H,     Bgl + ko);
        cp_async16(BsW + s*STAGE_H + 8, Bgl + ko + 8);
        asm volatile("cp.async.commit_group;\n");
    }

    for (int kc = 0; kc < NKC; kc++){
        // chunk kc must be resident
        if (kc < NKC-2)       asm volatile("cp.async.wait_group 2;\n");
        else if (kc == NKC-2) asm volatile("cp.async.wait_group 1;\n");
        else                  asm volatile("cp.async.wait_group 0;\n");
        __syncthreads();

        // prefetch chunk kc+3 into stage (kc+3)%4 == (kc-1)%4 (consumed last iter)
        if (kc + 3 < NKC){
            const int ns = (kc + 3) & (NSTAGE-1);
            const size_t ko = (size_t)(kc+3)*KC;
            cp_async16(AsW + ns*STAGE_H,     Agl + ko);
            cp_async16(AsW + ns*STAGE_H + 8, Agl + ko + 8);
            cp_async16(BsW + ns*STAGE_H,     Bgl + ko);
            cp_async16(BsW + ns*STAGE_H + 8, Bgl + ko + 8);
            asm volatile("cp.async.commit_group;\n");
        }

        const int s = kc & (NSTAGE-1);
        const uint32_t a_cta = as_base + (uint32_t)s*STAGE_H*2;
        const uint32_t b_cta = bs_base + (uint32_t)s*STAGE_H*2;
        const uint32_t a_base = a_cta + (uint32_t)(((wm*32 + a_row)*STRIDE + a_koff) * 2);
        const uint32_t b_base = b_cta + (uint32_t)(((wn*64 + b_row)*STRIDE + b_koff) * 2);

        #pragma unroll
        for (int ks = 0; ks < 2; ks++){
            uint32_t a[2][4], b[4][4];
            #pragma unroll
            for (int mi = 0; mi < 2; mi++)
                ldsm_x4(a[mi], a_base + (uint32_t)((mi*16*STRIDE + ks*16) * 2));
            #pragma unroll
            for (int p = 0; p < 4; p++)
                ldsm_x4(b[p], b_base + (uint32_t)((p*16*STRIDE + ks*16) * 2));
            #pragma unroll
            for (int p = 0; p < 4; p++){
                mma_fp16(c[0][2*p+0], a[0], b[p][0], b[p][1]);
                mma_fp16(c[1][2*p+0], a[1], b[p][0], b[p][1]);
                mma_fp16(c[0][2*p+1], a[0], b[p][2], b[p][3]);
                mma_fp16(c[1][2*p+1], a[1], b[p][2], b[p][3]);
            }
        }
    }
    __syncthreads();

    // epilogue: h = relu(acc + bias(b_row, col)); att += h .* Wf
    float attr[2][2] = {{0.f,0.f},{0.f,0.f}};
    #pragma unroll
    for (int ni = 0; ni < 8; ni++){
        const int cl = wn*64 + ni*8 + 2*t;               // local col
        const float w0 = wf_s[cl], w1 = wf_s[cl+1];
        #pragma unroll
        for (int mi = 0; mi < 2; mi++){
            #pragma unroll
            for (int rr = 0; rr < 2; rr++){
                const int rowg = m0 + wm*32 + mi*16 + g + rr*8;
                const int rb   = rowg / P_ - b_first;          // 0 or 1
                const float bv0 = bias_s[rb*128 + cl];
                const float bv1 = bias_s[rb*128 + cl + 1];
                const float h0 = fmaxf(c[mi][ni][rr*2+0] + bv0, 0.f);
                const float h1 = fmaxf(c[mi][ni][rr*2+1] + bv1, 0.f);
                attr[mi][rr] += h0*w0 + h1*w1;
            }
        }
    }
    #pragma unroll
    for (int mi = 0; mi < 2; mi++)
        #pragma unroll
        for (int rr = 0; rr < 2; rr++){
            float v = attr[mi][rr];
            v += __shfl_xor_sync(0xffffffffu, v, 1);
            v += __shfl_xor_sync(0xffffffffu, v, 2);
            if (t == 0) atomicAdd(&satt[wm*32 + mi*16 + g + rr*8], v);
        }
    __syncthreads();
    if (tid < 128) atomicAdd(&g_att[m0 + tid], satt[tid]);
}

// ---------------- kernel 4: softmax over P per batch row ----------------
__global__ void softmax_kernel(float* __restrict__ alpha_out){
    const int b = blockIdx.x, tid = threadIdx.x;    // 256 threads
    __shared__ float red[256];
    float v = (tid < P_) ? g_att[b*P_ + tid] : -1e30f;
    red[tid] = v; __syncthreads();
    for (int s = 128; s > 0; s >>= 1){
        if (tid < s) red[tid] = fmaxf(red[tid], red[tid+s]);
        __syncthreads();
    }
    const float mx = red[0]; __syncthreads();
    const float e = (tid < P_) ? expf(v - mx) : 0.f;
    red[tid] = e; __syncthreads();
    for (int s = 128; s > 0; s >>= 1){
        if (tid < s) red[tid] += red[tid+s];
        __syncthreads();
    }
    const float inv = 1.f / red[0];
    if (tid < P_) alpha_out[b*P_ + tid] = e * inv;
}

// ---------------- kernel 5: awe[b,e] = sum_p ench[b,p,e] * alpha[b,p] (fp16 enc) --------
__global__ void __launch_bounds__(512)
awe_kernel(const float* __restrict__ alpha, float4* __restrict__ out4){
    const int b = blockIdx.x, tid = threadIdx.x;    // 512 threads, 4 halves each
    __shared__ float al[P_];
    if (tid < P_) al[tid] = alpha[b*P_ + tid];
    __syncthreads();
    float4 acc = make_float4(0.f, 0.f, 0.f, 0.f);
    const uint2* ep = (const uint2*)(g_ench + (size_t)b * P_ * E_) + tid;
    #pragma unroll 4
    for (int p = 0; p < P_; p++){
        const float a = al[p];
        const uint2 u = ep[(size_t)p * (E_/4)];
        const __half2 h0 = *(const __half2*)&u.x;
        const __half2 h1 = *(const __half2*)&u.y;
        acc.x += a * __low2float(h0);  acc.y += a * __high2float(h0);
        acc.z += a * __low2float(h1);  acc.w += a * __high2float(h1);
    }
    out4[(size_t)b * (E_/4) + tid] = acc;
}

// ---------------- launch ----------------
extern "C" void kernel_launch(void* const* d_in, const int* in_sizes, int n_in,
                              void* d_out, int out_size){
    const float* enc  = (const float*)d_in[0];   // (B,P,E)
    const float* dh   = (const float*)d_in[1];   // (1,B,D)
    const float* We_w = (const float*)d_in[2];   // (E,A)
    const float* We_b = (const float*)d_in[3];   // (A)
    const float* Wd_w = (const float*)d_in[4];   // (D,A)
    const float* Wd_b = (const float*)d_in[5];   // (A)
    const float* Wf_w = (const float*)d_in[6];   // (A)
    // d_in[7] = Wf_b: scalar logit shift -> softmax-invariant, outputs don't depend on it.

    float* out       = (float*)d_out;
    float* awe_out   = out;                       // (B,E)
    float* alpha_out = out + (size_t)B_*E_;       // (B,P)

    cudaFuncSetAttribute(gemm_att_kernel, cudaFuncAttributeMaxDynamicSharedMemorySize, SMEM_BYTES);

    prep_bh       <<<dim3(E_/32, A_/32), dim3(32, 8)>>>(We_w);
    prep_ench     <<<(int)((size_t)MTOT*E_/(512*8)), 512>>>(enc);
    att2_kernel   <<<32, 128>>>(dh, Wd_w, Wd_b, We_b);
    gemm_att_kernel<<<(MTOT/MT)*NSPLIT, 256, SMEM_BYTES>>>(Wf_w);   // launch idx 3 -> ncu target
    softmax_kernel<<<B_, 256>>>(alpha_out);
    awe_kernel    <<<B_, 512>>>(alpha_out, (float4*)awe_out);
}

// round 10
// speedup vs baseline: 1.1140x; 1.0192x over previous
#include <cuda_runtime.h>
#include <cuda_fp16.h>
#include <cstdint>
#include <cstddef>

#define B_    256
#define P_    196
#define E_    2048
#define A_    512
#define MTOT  (B_*P_)      // 50176

// GEMM tiling: 128x128 tile, 256 threads, 2 CTAs/SM, 4-stage ring + reg-pipelined frags
#define MT 128
#define NT 128
#define KC 32
#define NKC (E_/KC)        // 64
#define NSPLIT (A_/NT)     // 4
#define STRIDE 40          // halves per smem row (80B -> conflict-free ldmatrix)
#define NSTAGE 4

// scratch
__device__ float  g_att2[B_*A_];   // dh@Wd + Wd_b + We_b combined bias
__device__ float  g_att [MTOT];    // logits
__device__ __half g_Bth [A_*E_];   // We transposed to [N][K], fp16 (2MB)
__device__ __half g_ench[(size_t)MTOT*E_];  // enc in fp16 (205MB)

// ---------------- helpers ----------------
__device__ __forceinline__ void cp_async16(void* smem_dst, const void* gmem_src){
    unsigned s = (unsigned)__cvta_generic_to_shared(smem_dst);
    asm volatile("cp.async.cg.shared.global [%0], [%1], 16;\n" :: "r"(s), "l"(gmem_src));
}
__device__ __forceinline__ uint32_t packh(float a, float b){
    __half2 h = __floats2half2_rn(a, b);
    return *reinterpret_cast<uint32_t*>(&h);
}
__device__ __forceinline__ void mma_fp16(float c[4], const uint32_t a[4], uint32_t b0, uint32_t b1){
    asm volatile(
        "mma.sync.aligned.m16n8k16.row.col.f32.f16.f16.f32 "
        "{%0,%1,%2,%3}, {%4,%5,%6,%7}, {%8,%9}, {%0,%1,%2,%3};\n"
        : "+f"(c[0]), "+f"(c[1]), "+f"(c[2]), "+f"(c[3])
        : "r"(a[0]), "r"(a[1]), "r"(a[2]), "r"(a[3]), "r"(b0), "r"(b1));
}
__device__ __forceinline__ void ldsm_x4(uint32_t r[4], uint32_t saddr){
    asm volatile("ldmatrix.sync.aligned.m8n8.x4.shared.b16 {%0,%1,%2,%3}, [%4];"
        : "=r"(r[0]), "=r"(r[1]), "=r"(r[2]), "=r"(r[3]) : "r"(saddr));
}
__device__ __forceinline__ uint32_t smem_u32(const void* p){
    return (uint32_t)__cvta_generic_to_shared(p);
}

// ---------------- kernel 0: g_Bth[n][k] = fp16(We[k][n]) ----------------
__global__ void prep_bh(const float* __restrict__ We){
    __shared__ float t[32][33];
    const int k0 = blockIdx.x*32, n0 = blockIdx.y*32;
    const int tx = threadIdx.x, ty = threadIdx.y;   // (32,8)
    #pragma unroll
    for (int i = 0; i < 4; i++)
        t[ty + i*8][tx] = We[(size_t)(k0 + ty + i*8)*A_ + n0 + tx];
    __syncthreads();
    #pragma unroll
    for (int i = 0; i < 4; i++)
        g_Bth[(size_t)(n0 + ty + i*8)*E_ + k0 + tx] = __float2half_rn(t[tx][ty + i*8]);
}

// ---------------- kernel 1: enc -> fp16 (streaming) + zero logits ----------------
__global__ void __launch_bounds__(512)
prep_ench(const float* __restrict__ enc){
    const size_t i = ((size_t)blockIdx.x*512 + threadIdx.x)*8;
    const float4 v0 = *(const float4*)(enc + i);
    const float4 v1 = *(const float4*)(enc + i + 4);
    uint4 w;
    w.x = packh(v0.x, v0.y);  w.y = packh(v0.z, v0.w);
    w.z = packh(v1.x, v1.y);  w.w = packh(v1.z, v1.w);
    *(uint4*)(g_ench + i) = w;
    const int j = blockIdx.x*512 + threadIdx.x;
    if (j < MTOT) g_att[j] = 0.f;
}

// ---------------- kernel 2: att2/bias ----------------
__global__ void att2_kernel(const float* __restrict__ dh,  const float* __restrict__ Wd,
                            const float* __restrict__ Wdb, const float* __restrict__ Web){
    __shared__ float dh_s[8][512];
    const int tid = threadIdx.x;
    const int bb  = blockIdx.x * 8;
    for (int i = tid; i < 8*512; i += 128)
        dh_s[i >> 9][i & 511] = dh[(size_t)bb*512 + i];
    __syncthreads();

    float acc[8][4];
    #pragma unroll
    for (int j = 0; j < 4; j++){
        float base = Wdb[tid + j*128] + Web[tid + j*128];
        #pragma unroll
        for (int q = 0; q < 8; q++) acc[q][j] = base;
    }
    for (int k = 0; k < 512; k++){
        #pragma unroll
        for (int j = 0; j < 4; j++){
            float w = Wd[(size_t)k*512 + tid + j*128];
            #pragma unroll
            for (int q = 0; q < 8; q++) acc[q][j] += dh_s[q][k] * w;
        }
    }
    #pragma unroll
    for (int q = 0; q < 8; q++)
        #pragma unroll
        for (int j = 0; j < 4; j++)
            g_att2[(size_t)(bb+q)*512 + tid + j*128] = acc[q][j];
}

// ---------------- kernel 3 (ncu idx 3): fp16 GEMM, reg-pipelined fragments ----------
#define STAGE_H (128*STRIDE)                         // 5120 halves = 10KB
#define STB     (STAGE_H*2)                          // stage bytes
#define AS_H    (NSTAGE*STAGE_H)
#define BS_H    (NSTAGE*STAGE_H)
#define EX_FLOATS (256 + 128 + 128)
#define SMEM_BYTES ((AS_H + BS_H)*2 + EX_FLOATS*4)   // 83968

#define LOAD_FRAGS(aa, bb, abase, bbase, ks) do {                                   \
    ldsm_x4(aa[0], (abase) + (uint32_t)((0*16*STRIDE + (ks)*16)*2));                \
    ldsm_x4(aa[1], (abase) + (uint32_t)((1*16*STRIDE + (ks)*16)*2));                \
    ldsm_x4(bb[0], (bbase) + (uint32_t)((0*16*STRIDE + (ks)*16)*2));                \
    ldsm_x4(bb[1], (bbase) + (uint32_t)((1*16*STRIDE + (ks)*16)*2));                \
    ldsm_x4(bb[2], (bbase) + (uint32_t)((2*16*STRIDE + (ks)*16)*2));                \
    ldsm_x4(bb[3], (bbase) + (uint32_t)((3*16*STRIDE + (ks)*16)*2));                \
} while(0)

#define MMA_SET(aa, bb) do {                                                        \
    _Pragma("unroll")                                                               \
    for (int p = 0; p < 4; p++){                                                    \
        mma_fp16(c[0][2*p+0], aa[0], bb[p][0], bb[p][1]);                           \
        mma_fp16(c[1][2*p+0], aa[1], bb[p][0], bb[p][1]);                           \
        mma_fp16(c[0][2*p+1], aa[0], bb[p][2], bb[p][3]);                           \
        mma_fp16(c[1][2*p+1], aa[1], bb[p][2], bb[p][3]);                           \
    }                                                                               \
} while(0)

__global__ void __launch_bounds__(256, 2)
gemm_att_kernel(const float* __restrict__ Wf){
    extern __shared__ char smraw[];
    __half* As     = (__half*)smraw;
    __half* Bs     = As + AS_H;
    float*  bias_s = (float*)(smraw + (AS_H + BS_H)*2);   // [2][128]
    float*  wf_s   = bias_s + 256;
    float*  satt   = wf_s + 128;

    const int tid = threadIdx.x;
    const int bid = blockIdx.x;
    const int m0  = (bid >> 2) * MT;
    const int n0  = (bid & 3)  * NT;
    const int b_first = m0 / P_;

    {
        int j = tid >> 7, c2 = tid & 127;                 // 2 x 128
        int b = b_first + j;
        bias_s[tid] = (b < B_) ? g_att2[(size_t)b*A_ + n0 + c2] : 0.f;
        if (tid < 128){ wf_s[tid] = Wf[n0 + tid]; satt[tid] = 0.f; }
    }

    const int warp = tid >> 5, lane = tid & 31;
    const int wm = warp >> 1, wn = warp & 1;        // 4x2 warp grid; warp tile 32x64
    const int g = lane >> 2, t = lane & 3;

    const uint32_t as_base = smem_u32(As);
    const uint32_t bs_base = smem_u32(Bs);

    // ldmatrix lane addressing (halves)
    const int a_row  = lane & 15;
    const int a_koff = (lane >> 4) * 8;
    const int b_row  = (lane & 7) + ((lane >> 4) & 1) * 8;
    const int b_koff = ((lane >> 3) & 1) * 8;
    const uint32_t awoff = (uint32_t)(((wm*32 + a_row)*STRIDE + a_koff) * 2);
    const uint32_t bwoff = (uint32_t)(((wn*64 + b_row)*STRIDE + b_koff) * 2);

    // staging addressing: thread covers 2x16B (A) + 2x16B (B) per chunk
    const int ld_row = tid >> 1;
    const int ld_sg  = (tid & 1) * 2;
    const __half* Agl = g_ench + (size_t)(m0 + ld_row)*E_ + ld_sg*8;
    const __half* Bgl = g_Bth  + (size_t)(n0 + ld_row)*E_ + ld_sg*8;
    __half* AsW = As + ld_row*STRIDE + ld_sg*8;
    __half* BsW = Bs + ld_row*STRIDE + ld_sg*8;

    float c[2][8][4];
    #pragma unroll
    for (int mi = 0; mi < 2; mi++)
        #pragma unroll
        for (int ni = 0; ni < 8; ni++)
            #pragma unroll
            for (int j = 0; j < 4; j++) c[mi][ni][j] = 0.f;

    // ---- prologue: stage chunks 0..2 into stages 0..2 ----
    #pragma unroll
    for (int s = 0; s < 3; s++){
        const size_t ko = (size_t)s*KC;
        cp_async16(AsW + s*STAGE_H,     Agl + ko);
        cp_async16(AsW + s*STAGE_H + 8, Agl + ko + 8);
        cp_async16(BsW + s*STAGE_H,     Bgl + ko);
        cp_async16(BsW + s*STAGE_H + 8, Bgl + ko + 8);
        asm volatile("cp.async.commit_group;\n");
    }

    uint32_t a0[2][4], b0[4][4], a1[2][4], b1[4][4];

    // chunks 0 and 1 visible after this wait+barrier
    asm volatile("cp.async.wait_group 1;\n");
    __syncthreads();
    LOAD_FRAGS(a0, b0, as_base + awoff, bs_base + bwoff, 0);

    for (int kc = 0; kc < NKC; kc++){
        if (kc > 0){
            if (kc <= NKC-3) asm volatile("cp.async.wait_group 1;\n");
            else             asm volatile("cp.async.wait_group 0;\n");
            __syncthreads();
        }
        // prefetch chunk kc+3 into stage (kc+3)&3 (consumed at iter kc-1)
        if (kc + 3 < NKC){
            const int ns = (kc + 3) & (NSTAGE-1);
            const size_t ko = (size_t)(kc+3)*KC;
            cp_async16(AsW + ns*STAGE_H,     Agl + ko);
            cp_async16(AsW + ns*STAGE_H + 8, Agl + ko + 8);
            cp_async16(BsW + ns*STAGE_H,     Bgl + ko);
            cp_async16(BsW + ns*STAGE_H + 8, Bgl + ko + 8);
            asm volatile("cp.async.commit_group;\n");
        }

        const uint32_t sa  = as_base + (uint32_t)(kc & 3)*STB + awoff;
        const uint32_t sb  = bs_base + (uint32_t)(kc & 3)*STB + bwoff;

        // k-step 1 fragments prefetch, then MMA on k-step 0
        LOAD_FRAGS(a1, b1, sa, sb, 1);
        MMA_SET(a0, b0);

        // next chunk's k-step 0 fragments prefetch (chunk kc+1 is visible), then MMA on k-step 1
        if (kc + 1 < NKC){
            const uint32_t sa1 = as_base + (uint32_t)((kc+1) & 3)*STB + awoff;
            const uint32_t sb1 = bs_base + (uint32_t)((kc+1) & 3)*STB + bwoff;
            LOAD_FRAGS(a0, b0, sa1, sb1, 0);
        }
        MMA_SET(a1, b1);
    }
    __syncthreads();

    // epilogue: h = relu(acc + bias(b_row, col)); att += h .* Wf
    float attr[2][2] = {{0.f,0.f},{0.f,0.f}};
    #pragma unroll
    for (int ni = 0; ni < 8; ni++){
        const int cl = wn*64 + ni*8 + 2*t;               // local col
        const float w0 = wf_s[cl], w1 = wf_s[cl+1];
        #pragma unroll
        for (int mi = 0; mi < 2; mi++){
            #pragma unroll
            for (int rr = 0; rr < 2; rr++){
                const int rowg = m0 + wm*32 + mi*16 + g + rr*8;
                const int rb   = rowg / P_ - b_first;          // 0 or 1
                const float bv0 = bias_s[rb*128 + cl];
                const float bv1 = bias_s[rb*128 + cl + 1];
                const float h0 = fmaxf(c[mi][ni][rr*2+0] + bv0, 0.f);
                const float h1 = fmaxf(c[mi][ni][rr*2+1] + bv1, 0.f);
                attr[mi][rr] += h0*w0 + h1*w1;
            }
        }
    }
    #pragma unroll
    for (int mi = 0; mi < 2; mi++)
        #pragma unroll
        for (int rr = 0; rr < 2; rr++){
            float v = attr[mi][rr];
            v += __shfl_xor_sync(0xffffffffu, v, 1);
            v += __shfl_xor_sync(0xffffffffu, v, 2);
            if (t == 0) atomicAdd(&satt[wm*32 + mi*16 + g + rr*8], v);
        }
    __syncthreads();
    if (tid < 128) atomicAdd(&g_att[m0 + tid], satt[tid]);
}

// ---------------- kernel 4: softmax over P per batch row ----------------
__global__ void softmax_kernel(float* __restrict__ alpha_out){
    const int b = blockIdx.x, tid = threadIdx.x;    // 256 threads
    __shared__ float red[256];
    float v = (tid < P_) ? g_att[b*P_ + tid] : -1e30f;
    red[tid] = v; __syncthreads();
    for (int s = 128; s > 0; s >>= 1){
        if (tid < s) red[tid] = fmaxf(red[tid], red[tid+s]);
        __syncthreads();
    }
    const float mx = red[0]; __syncthreads();
    const float e = (tid < P_) ? expf(v - mx) : 0.f;
    red[tid] = e; __syncthreads();
    for (int s = 128; s > 0; s >>= 1){
        if (tid < s) red[tid] += red[tid+s];
        __syncthreads();
    }
    const float inv = 1.f / red[0];
    if (tid < P_) alpha_out[b*P_ + tid] = e * inv;
}

// ---------------- kernel 5: awe[b,e] = sum_p ench[b,p,e] * alpha[b,p] (fp16 enc) --------
__global__ void __launch_bounds__(512)
awe_kernel(const float* __restrict__ alpha, float4* __restrict__ out4){
    const int b = blockIdx.x, tid = threadIdx.x;    // 512 threads, 4 halves each
    __shared__ float al[P_];
    if (tid < P_) al[tid] = alpha[b*P_ + tid];
    __syncthreads();
    float4 acc = make_float4(0.f, 0.f, 0.f, 0.f);
    const uint2* ep = (const uint2*)(g_ench + (size_t)b * P_ * E_) + tid;
    #pragma unroll 4
    for (int p = 0; p < P_; p++){
        const float a = al[p];
        const uint2 u = ep[(size_t)p * (E_/4)];
        const __half2 h0 = *(const __half2*)&u.x;
        const __half2 h1 = *(const __half2*)&u.y;
        acc.x += a * __low2float(h0);  acc.y += a * __high2float(h0);
        acc.z += a * __low2float(h1);  acc.w += a * __high2float(h1);
    }
    out4[(size_t)b * (E_/4) + tid] = acc;
}

// ---------------- launch ----------------
extern "C" void kernel_launch(void* const* d_in, const int* in_sizes, int n_in,
                              void* d_out, int out_size){
    const float* enc  = (const float*)d_in[0];   // (B,P,E)
    const float* dh   = (const float*)d_in[1];   // (1,B,D)
    const float* We_w = (const float*)d_in[2];   // (E,A)
    const float* We_b = (const float*)d_in[3];   // (A)
    const float* Wd_w = (const float*)d_in[4];   // (D,A)
    const float* Wd_b = (const float*)d_in[5];   // (A)
    const float* Wf_w = (const float*)d_in[6];   // (A)
    // d_in[7] = Wf_b: scalar logit shift -> softmax-invariant, outputs don't depend on it.

    float* out       = (float*)d_out;
    float* awe_out   = out;                       // (B,E)
    float* alpha_out = out + (size_t)B_*E_;       // (B,P)

    cudaFuncSetAttribute(gemm_att_kernel, cudaFuncAttributeMaxDynamicSharedMemorySize, SMEM_BYTES);

    prep_bh       <<<dim3(E_/32, A_/32), dim3(32, 8)>>>(We_w);
    prep_ench     <<<(int)((size_t)MTOT*E_/(512*8)), 512>>>(enc);
    att2_kernel   <<<32, 128>>>(dh, Wd_w, Wd_b, We_b);
    gemm_att_kernel<<<(MTOT/MT)*NSPLIT, 256, SMEM_BYTES>>>(Wf_w);   // launch idx 3 -> ncu target
    softmax_kernel<<<B_, 256>>>(alpha_out);
    awe_kernel    <<<B_, 512>>>(alpha_out, (float4*)awe_out);
}

// round 11
// speedup vs baseline: 1.2878x; 1.1560x over previous
#include <cuda_runtime.h>
#include <cuda_fp16.h>
#include <cstdint>
#include <cstddef>

#define B_    256
#define P_    196
#define E_    2048
#define A_    512
#define MTOT  (B_*P_)      // 50176

// GEMM tiling: 128x128 tile, 256 threads, 2 CTAs/SM, 5-stage ring, sync every 2 chunks
#define MT 128
#define NT 128
#define KC 32
#define NKC (E_/KC)        // 64
#define NSPLIT (A_/NT)     // 4
#define STRIDE 40          // halves per smem row (80B -> conflict-free ldmatrix)
#define NSTAGE 5

// scratch
__device__ float  g_att2[B_*A_];   // dh@Wd + Wd_b + We_b combined bias
__device__ float  g_att [MTOT];    // logits
__device__ __half g_Bth [A_*E_];   // We transposed to [N][K], fp16 (2MB)
__device__ __half g_ench[(size_t)MTOT*E_];  // enc in fp16 (205MB)

// ---------------- helpers ----------------
__device__ __forceinline__ void cp_async16(void* smem_dst, const void* gmem_src){
    unsigned s = (unsigned)__cvta_generic_to_shared(smem_dst);
    asm volatile("cp.async.cg.shared.global [%0], [%1], 16;\n" :: "r"(s), "l"(gmem_src));
}
__device__ __forceinline__ uint32_t packh(float a, float b){
    __half2 h = __floats2half2_rn(a, b);
    return *reinterpret_cast<uint32_t*>(&h);
}
__device__ __forceinline__ void mma_fp16(float c[4], const uint32_t a[4], uint32_t b0, uint32_t b1){
    asm volatile(
        "mma.sync.aligned.m16n8k16.row.col.f32.f16.f16.f32 "
        "{%0,%1,%2,%3}, {%4,%5,%6,%7}, {%8,%9}, {%0,%1,%2,%3};\n"
        : "+f"(c[0]), "+f"(c[1]), "+f"(c[2]), "+f"(c[3])
        : "r"(a[0]), "r"(a[1]), "r"(a[2]), "r"(a[3]), "r"(b0), "r"(b1));
}
__device__ __forceinline__ void ldsm_x4(uint32_t r[4], uint32_t saddr){
    asm volatile("ldmatrix.sync.aligned.m8n8.x4.shared.b16 {%0,%1,%2,%3}, [%4];"
        : "=r"(r[0]), "=r"(r[1]), "=r"(r[2]), "=r"(r[3]) : "r"(saddr));
}
__device__ __forceinline__ uint32_t smem_u32(const void* p){
    return (uint32_t)__cvta_generic_to_shared(p);
}

// ---------------- kernel 0: g_Bth[n][k] = fp16(We[k][n]) ----------------
__global__ void prep_bh(const float* __restrict__ We){
    __shared__ float t[32][33];
    const int k0 = blockIdx.x*32, n0 = blockIdx.y*32;
    const int tx = threadIdx.x, ty = threadIdx.y;   // (32,8)
    #pragma unroll
    for (int i = 0; i < 4; i++)
        t[ty + i*8][tx] = We[(size_t)(k0 + ty + i*8)*A_ + n0 + tx];
    __syncthreads();
    #pragma unroll
    for (int i = 0; i < 4; i++)
        g_Bth[(size_t)(n0 + ty + i*8)*E_ + k0 + tx] = __float2half_rn(t[tx][ty + i*8]);
}

// ---------------- kernel 1: enc -> fp16 (streaming) + zero logits ----------------
__global__ void __launch_bounds__(512)
prep_ench(const float* __restrict__ enc){
    const size_t i = ((size_t)blockIdx.x*512 + threadIdx.x)*8;
    const float4 v0 = *(const float4*)(enc + i);
    const float4 v1 = *(const float4*)(enc + i + 4);
    uint4 w;
    w.x = packh(v0.x, v0.y);  w.y = packh(v0.z, v0.w);
    w.z = packh(v1.x, v1.y);  w.w = packh(v1.z, v1.w);
    *(uint4*)(g_ench + i) = w;
    const int j = blockIdx.x*512 + threadIdx.x;
    if (j < MTOT) g_att[j] = 0.f;
}

// ---------------- kernel 2: att2/bias (64 blocks, 4 batches each) ----------------
__global__ void __launch_bounds__(256)
att2_kernel(const float* __restrict__ dh,  const float* __restrict__ Wd,
            const float* __restrict__ Wdb, const float* __restrict__ Web){
    __shared__ float dh_s[4][512];
    const int tid = threadIdx.x;
    const int bb  = blockIdx.x * 4;
    for (int i = tid; i < 4*512; i += 256)
        dh_s[i >> 9][i & 511] = dh[(size_t)bb*512 + i];
    __syncthreads();

    float acc[4][2];
    {
        const float base0 = Wdb[tid]       + Web[tid];
        const float base1 = Wdb[tid + 256] + Web[tid + 256];
        #pragma unroll
        for (int q = 0; q < 4; q++){ acc[q][0] = base0; acc[q][1] = base1; }
    }
    for (int k = 0; k < 512; k++){
        const float w0 = Wd[(size_t)k*512 + tid];
        const float w1 = Wd[(size_t)k*512 + tid + 256];
        #pragma unroll
        for (int q = 0; q < 4; q++){
            const float d = dh_s[q][k];
            acc[q][0] += d * w0;
            acc[q][1] += d * w1;
        }
    }
    #pragma unroll
    for (int q = 0; q < 4; q++){
        g_att2[(size_t)(bb+q)*512 + tid]       = acc[q][0];
        g_att2[(size_t)(bb+q)*512 + tid + 256] = acc[q][1];
    }
}

// ---------------- kernel 3 (ncu idx 3): fp16 GEMM, 5-stage ring, 1 sync / 2 chunks ----
#define STAGE_H (128*STRIDE)                         // 5120 halves = 10KB
#define STB     (STAGE_H*2)                          // stage bytes
#define AS_H    (NSTAGE*STAGE_H)
#define BS_H    (NSTAGE*STAGE_H)
#define EX_FLOATS (256 + 128 + 128)
#define SMEM_BYTES ((AS_H + BS_H)*2 + EX_FLOATS*4)   // 104448

#define LOAD_FRAGS(aa, bb, abase, bbase, ks) do {                                   \
    ldsm_x4(aa[0], (abase) + (uint32_t)((0*16*STRIDE + (ks)*16)*2));                \
    ldsm_x4(aa[1], (abase) + (uint32_t)((1*16*STRIDE + (ks)*16)*2));                \
    ldsm_x4(bb[0], (bbase) + (uint32_t)((0*16*STRIDE + (ks)*16)*2));                \
    ldsm_x4(bb[1], (bbase) + (uint32_t)((1*16*STRIDE + (ks)*16)*2));                \
    ldsm_x4(bb[2], (bbase) + (uint32_t)((2*16*STRIDE + (ks)*16)*2));                \
    ldsm_x4(bb[3], (bbase) + (uint32_t)((3*16*STRIDE + (ks)*16)*2));                \
} while(0)

#define MMA_SET(aa, bb) do {                                                        \
    _Pragma("unroll")                                                               \
    for (int p = 0; p < 4; p++){                                                    \
        mma_fp16(c[0][2*p+0], aa[0], bb[p][0], bb[p][1]);                           \
        mma_fp16(c[1][2*p+0], aa[1], bb[p][0], bb[p][1]);                           \
        mma_fp16(c[0][2*p+1], aa[0], bb[p][2], bb[p][3]);                           \
        mma_fp16(c[1][2*p+1], aa[1], bb[p][2], bb[p][3]);                           \
    }                                                                               \
} while(0)

#define PREFETCH(ck, st) do {                                                       \
    const size_t ko = (size_t)(ck)*KC;                                              \
    cp_async16(AsW + (st)*STAGE_H,     Agl + ko);                                   \
    cp_async16(AsW + (st)*STAGE_H + 8, Agl + ko + 8);                               \
    cp_async16(BsW + (st)*STAGE_H,     Bgl + ko);                                   \
    cp_async16(BsW + (st)*STAGE_H + 8, Bgl + ko + 8);                               \
    asm volatile("cp.async.commit_group;\n");                                       \
} while(0)

__global__ void __launch_bounds__(256, 2)
gemm_att_kernel(const float* __restrict__ Wf){
    extern __shared__ char smraw[];
    __half* As     = (__half*)smraw;
    __half* Bs     = As + AS_H;
    float*  bias_s = (float*)(smraw + (AS_H + BS_H)*2);   // [2][128]
    float*  wf_s   = bias_s + 256;
    float*  satt   = wf_s + 128;

    const int tid = threadIdx.x;
    const int bid = blockIdx.x;
    const int m0  = (bid >> 2) * MT;
    const int n0  = (bid & 3)  * NT;
    const int b_first = m0 / P_;

    {
        int j = tid >> 7, c2 = tid & 127;                 // 2 x 128
        int b = b_first + j;
        bias_s[tid] = (b < B_) ? g_att2[(size_t)b*A_ + n0 + c2] : 0.f;
        if (tid < 128){ wf_s[tid] = Wf[n0 + tid]; satt[tid] = 0.f; }
    }

    const int warp = tid >> 5, lane = tid & 31;
    const int wm = warp >> 1, wn = warp & 1;        // 4x2 warp grid; warp tile 32x64
    const int g = lane >> 2, t = lane & 3;

    const uint32_t as_base = smem_u32(As);
    const uint32_t bs_base = smem_u32(Bs);

    // ldmatrix lane addressing (halves)
    const int a_row  = lane & 15;
    const int a_koff = (lane >> 4) * 8;
    const int b_row  = (lane & 7) + ((lane >> 4) & 1) * 8;
    const int b_koff = ((lane >> 3) & 1) * 8;
    const uint32_t awoff = (uint32_t)(((wm*32 + a_row)*STRIDE + a_koff) * 2);
    const uint32_t bwoff = (uint32_t)(((wn*64 + b_row)*STRIDE + b_koff) * 2);

    // staging addressing: thread covers 2x16B (A) + 2x16B (B) per chunk
    const int ld_row = tid >> 1;
    const int ld_sg  = (tid & 1) * 2;
    const __half* Agl = g_ench + (size_t)(m0 + ld_row)*E_ + ld_sg*8;
    const __half* Bgl = g_Bth  + (size_t)(n0 + ld_row)*E_ + ld_sg*8;
    __half* AsW = As + ld_row*STRIDE + ld_sg*8;
    __half* BsW = Bs + ld_row*STRIDE + ld_sg*8;

    float c[2][8][4];
    #pragma unroll
    for (int mi = 0; mi < 2; mi++)
        #pragma unroll
        for (int ni = 0; ni < 8; ni++)
            #pragma unroll
            for (int j = 0; j < 4; j++) c[mi][ni][j] = 0.f;

    // ---- prologue: stage chunks 0..2 into stages 0..2, make them visible ----
    PREFETCH(0, 0);
    PREFETCH(1, 1);
    PREFETCH(2, 2);
    asm volatile("cp.async.wait_group 0;\n");
    __syncthreads();

    uint32_t a0[2][4], b0[4][4], a1[2][4], b1[4][4];
    LOAD_FRAGS(a0, b0, as_base + awoff, bs_base + bwoff, 0);   // chunk 0, k-step 0

    int scur = 0;                                   // stage of chunk kb
    for (int kb = 0; kb < NKC; kb += 2){
        if (kb > 0){
            // drain all outstanding (chunks <= kb+2), one barrier per 2 chunks
            asm volatile("cp.async.wait_group 0;\n");
            __syncthreads();
        }
        int s1 = scur + 1; if (s1 >= NSTAGE) s1 -= NSTAGE;     // chunk kb+1
        int s2 = s1 + 1;   if (s2 >= NSTAGE) s2 -= NSTAGE;     // chunk kb+2
        int w0 = s2 + 1;   if (w0 >= NSTAGE) w0 -= NSTAGE;     // chunk kb+3
        int w1 = w0 + 1;   if (w1 >= NSTAGE) w1 -= NSTAGE;     // chunk kb+4

        if (kb + 3 < NKC) PREFETCH(kb + 3, w0);

        const uint32_t sa0 = as_base + (uint32_t)scur*STB + awoff;
        const uint32_t sb0 = bs_base + (uint32_t)scur*STB + bwoff;
        const uint32_t sa1 = as_base + (uint32_t)s1*STB + awoff;
        const uint32_t sb1 = bs_base + (uint32_t)s1*STB + bwoff;

        // chunk kb
        LOAD_FRAGS(a1, b1, sa0, sb0, 1);
        MMA_SET(a0, b0);
        LOAD_FRAGS(a0, b0, sa1, sb1, 0);
        MMA_SET(a1, b1);

        if (kb + 4 < NKC) PREFETCH(kb + 4, w1);

        // chunk kb+1
        LOAD_FRAGS(a1, b1, sa1, sb1, 1);
        MMA_SET(a0, b0);
        if (kb + 2 < NKC){
            const uint32_t sa2 = as_base + (uint32_t)s2*STB + awoff;
            const uint32_t sb2 = bs_base + (uint32_t)s2*STB + bwoff;
            LOAD_FRAGS(a0, b0, sa2, sb2, 0);
        }
        MMA_SET(a1, b1);

        scur = s2;
    }
    __syncthreads();

    // epilogue: h = relu(acc + bias(b_row, col)); att += h .* Wf
    float attr[2][2] = {{0.f,0.f},{0.f,0.f}};
    #pragma unroll
    for (int ni = 0; ni < 8; ni++){
        const int cl = wn*64 + ni*8 + 2*t;               // local col
        const float w0 = wf_s[cl], w1 = wf_s[cl+1];
        #pragma unroll
        for (int mi = 0; mi < 2; mi++){
            #pragma unroll
            for (int rr = 0; rr < 2; rr++){
                const int rowg = m0 + wm*32 + mi*16 + g + rr*8;
                const int rb   = rowg / P_ - b_first;          // 0 or 1
                const float bv0 = bias_s[rb*128 + cl];
                const float bv1 = bias_s[rb*128 + cl + 1];
                const float h0 = fmaxf(c[mi][ni][rr*2+0] + bv0, 0.f);
                const float h1 = fmaxf(c[mi][ni][rr*2+1] + bv1, 0.f);
                attr[mi][rr] += h0*w0 + h1*w1;
            }
        }
    }
    #pragma unroll
    for (int mi = 0; mi < 2; mi++)
        #pragma unroll
        for (int rr = 0; rr < 2; rr++){
            float v = attr[mi][rr];
            v += __shfl_xor_sync(0xffffffffu, v, 1);
            v += __shfl_xor_sync(0xffffffffu, v, 2);
            if (t == 0) atomicAdd(&satt[wm*32 + mi*16 + g + rr*8], v);
        }
    __syncthreads();
    if (tid < 128) atomicAdd(&g_att[m0 + tid], satt[tid]);
}

// ---------------- kernel 4: softmax over P per batch row ----------------
__global__ void softmax_kernel(float* __restrict__ alpha_out){
    const int b = blockIdx.x, tid = threadIdx.x;    // 256 threads
    __shared__ float red[256];
    float v = (tid < P_) ? g_att[b*P_ + tid] : -1e30f;
    red[tid] = v; __syncthreads();
    for (int s = 128; s > 0; s >>= 1){
        if (tid < s) red[tid] = fmaxf(red[tid], red[tid+s]);
        __syncthreads();
    }
    const float mx = red[0]; __syncthreads();
    const float e = (tid < P_) ? expf(v - mx) : 0.f;
    red[tid] = e; __syncthreads();
    for (int s = 128; s > 0; s >>= 1){
        if (tid < s) red[tid] += red[tid+s];
        __syncthreads();
    }
    const float inv = 1.f / red[0];
    if (tid < P_) alpha_out[b*P_ + tid] = e * inv;
}

// ---------------- kernel 5: awe[b,e] = sum_p ench[b,p,e] * alpha[b,p] (fp16 enc) --------
__global__ void __launch_bounds__(512)
awe_kernel(const float* __restrict__ alpha, float4* __restrict__ out4){
    const int b = blockIdx.x, tid = threadIdx.x;    // 512 threads, 4 halves each
    __shared__ float al[P_];
    if (tid < P_) al[tid] = alpha[b*P_ + tid];
    __syncthreads();
    float4 acc = make_float4(0.f, 0.f, 0.f, 0.f);
    const uint2* ep = (const uint2*)(g_ench + (size_t)b * P_ * E_) + tid;
    #pragma unroll 4
    for (int p = 0; p < P_; p++){
        const float a = al[p];
        const uint2 u = ep[(size_t)p * (E_/4)];
        const __half2 h0 = *(const __half2*)&u.x;
        const __half2 h1 = *(const __half2*)&u.y;
        acc.x += a * __low2float(h0);  acc.y += a * __high2float(h0);
        acc.z += a * __low2float(h1);  acc.w += a * __high2float(h1);
    }
    out4[(size_t)b * (E_/4) + tid] = acc;
}

// ---------------- launch ----------------
extern "C" void kernel_launch(void* const* d_in, const int* in_sizes, int n_in,
                              void* d_out, int out_size){
    const float* enc  = (const float*)d_in[0];   // (B,P,E)
    const float* dh   = (const float*)d_in[1];   // (1,B,D)
    const float* We_w = (const float*)d_in[2];   // (E,A)
    const float* We_b = (const float*)d_in[3];   // (A)
    const float* Wd_w = (const float*)d_in[4];   // (D,A)
    const float* Wd_b = (const float*)d_in[5];   // (A)
    const float* Wf_w = (const float*)d_in[6];   // (A)
    // d_in[7] = Wf_b: scalar logit shift -> softmax-invariant, outputs don't depend on it.

    float* out       = (float*)d_out;
    float* awe_out   = out;                       // (B,E)
    float* alpha_out = out + (size_t)B_*E_;       // (B,P)

    cudaFuncSetAttribute(gemm_att_kernel, cudaFuncAttributeMaxDynamicSharedMemorySize, SMEM_BYTES);

    prep_bh       <<<dim3(E_/32, A_/32), dim3(32, 8)>>>(We_w);
    prep_ench     <<<(int)((size_t)MTOT*E_/(512*8)), 512>>>(enc);
    att2_kernel   <<<64, 256>>>(dh, Wd_w, Wd_b, We_b);
    gemm_att_kernel<<<(MTOT/MT)*NSPLIT, 256, SMEM_BYTES>>>(Wf_w);   // launch idx 3 -> ncu target
    softmax_kernel<<<B_, 256>>>(alpha_out);
    awe_kernel    <<<B_, 512>>>(alpha_out, (float4*)awe_out);
}

// round 12
// speedup vs baseline: 1.3904x; 1.0797x over previous
#include <cuda_runtime.h>
#include <cuda_fp16.h>
#include <cstdint>
#include <cstddef>

#define B_    256
#define P_    196
#define E_    2048
#define A_    512
#define MTOT  (B_*P_)      // 50176

// GEMM tiling: 128x128 tile, 256 threads, 2 CTAs/SM, 6-stage swizzled ring, sync / 3 chunks
#define MT 128
#define NT 128
#define KC 32
#define NKC (E_/KC)        // 64
#define NSPLIT (A_/NT)     // 4
#define NSTAGE 6
#define TILE_B 8192        // 128 rows x 64B (swizzled, no padding)

// scratch
__device__ float  g_att2[B_*A_];   // dh@Wd + Wd_b + We_b combined bias
__device__ float  g_att [MTOT];    // logits
__device__ __half g_Bth [A_*E_];   // We transposed to [N][K], fp16 (2MB)
__device__ __half g_ench[(size_t)MTOT*E_];  // enc in fp16 (205MB)

// ---------------- helpers ----------------
__device__ __forceinline__ void cp_async16(void* smem_dst, const void* gmem_src){
    unsigned s = (unsigned)__cvta_generic_to_shared(smem_dst);
    asm volatile("cp.async.cg.shared.global [%0], [%1], 16;\n" :: "r"(s), "l"(gmem_src));
}
__device__ __forceinline__ uint32_t packh(float a, float b){
    __half2 h = __floats2half2_rn(a, b);
    return *reinterpret_cast<uint32_t*>(&h);
}
__device__ __forceinline__ void mma_fp16(float c[4], const uint32_t a[4], uint32_t b0, uint32_t b1){
    asm volatile(
        "mma.sync.aligned.m16n8k16.row.col.f32.f16.f16.f32 "
        "{%0,%1,%2,%3}, {%4,%5,%6,%7}, {%8,%9}, {%0,%1,%2,%3};\n"
        : "+f"(c[0]), "+f"(c[1]), "+f"(c[2]), "+f"(c[3])
        : "r"(a[0]), "r"(a[1]), "r"(a[2]), "r"(a[3]), "r"(b0), "r"(b1));
}
__device__ __forceinline__ void ldsm_x4(uint32_t r[4], uint32_t saddr){
    asm volatile("ldmatrix.sync.aligned.m8n8.x4.shared.b16 {%0,%1,%2,%3}, [%4];"
        : "=r"(r[0]), "=r"(r[1]), "=r"(r[2]), "=r"(r[3]) : "r"(saddr));
}
__device__ __forceinline__ uint32_t smem_u32(const void* p){
    return (uint32_t)__cvta_generic_to_shared(p);
}

// ---------------- kernel 0: g_Bth[n][k] = fp16(We[k][n]) ----------------
__global__ void prep_bh(const float* __restrict__ We){
    __shared__ float t[32][33];
    const int k0 = blockIdx.x*32, n0 = blockIdx.y*32;
    const int tx = threadIdx.x, ty = threadIdx.y;   // (32,8)
    #pragma unroll
    for (int i = 0; i < 4; i++)
        t[ty + i*8][tx] = We[(size_t)(k0 + ty + i*8)*A_ + n0 + tx];
    __syncthreads();
    #pragma unroll
    for (int i = 0; i < 4; i++)
        g_Bth[(size_t)(n0 + ty + i*8)*E_ + k0 + tx] = __float2half_rn(t[tx][ty + i*8]);
}

// ---------------- kernel 1: enc -> fp16 (streaming) + zero logits ----------------
__global__ void __launch_bounds__(512)
prep_ench(const float* __restrict__ enc){
    const size_t i = ((size_t)blockIdx.x*512 + threadIdx.x)*8;
    const float4 v0 = *(const float4*)(enc + i);
    const float4 v1 = *(const float4*)(enc + i + 4);
    uint4 w;
    w.x = packh(v0.x, v0.y);  w.y = packh(v0.z, v0.w);
    w.z = packh(v1.x, v1.y);  w.w = packh(v1.z, v1.w);
    *(uint4*)(g_ench + i) = w;
    const int j = blockIdx.x*512 + threadIdx.x;
    if (j < MTOT) g_att[j] = 0.f;
}

// ---------------- kernel 2: att2/bias (64 blocks, 4 batches each) ----------------
__global__ void __launch_bounds__(256)
att2_kernel(const float* __restrict__ dh,  const float* __restrict__ Wd,
            const float* __restrict__ Wdb, const float* __restrict__ Web){
    __shared__ float dh_s[4][512];
    const int tid = threadIdx.x;
    const int bb  = blockIdx.x * 4;
    for (int i = tid; i < 4*512; i += 256)
        dh_s[i >> 9][i & 511] = dh[(size_t)bb*512 + i];
    __syncthreads();

    float acc[4][2];
    {
        const float base0 = Wdb[tid]       + Web[tid];
        const float base1 = Wdb[tid + 256] + Web[tid + 256];
        #pragma unroll
        for (int q = 0; q < 4; q++){ acc[q][0] = base0; acc[q][1] = base1; }
    }
    for (int k = 0; k < 512; k++){
        const float w0 = Wd[(size_t)k*512 + tid];
        const float w1 = Wd[(size_t)k*512 + tid + 256];
        #pragma unroll
        for (int q = 0; q < 4; q++){
            const float d = dh_s[q][k];
            acc[q][0] += d * w0;
            acc[q][1] += d * w1;
        }
    }
    #pragma unroll
    for (int q = 0; q < 4; q++){
        g_att2[(size_t)(bb+q)*512 + tid]       = acc[q][0];
        g_att2[(size_t)(bb+q)*512 + tid + 256] = acc[q][1];
    }
}

// ---------------- kernel 3 (ncu idx 3): fp16 GEMM, swizzled 6-stage ring ----------
// smem: A[6][8KB] | B[6][8KB] | bias[2][128] | wf[128] | satt[128]
#define EX_OFF  (2*NSTAGE*TILE_B)                    // 98304
#define SMEM_BYTES (EX_OFF + (256 + 128 + 128)*4)    // 100352

// swizzled byte offset within a tile: row*64 + ((chunk ^ ((row>>1)&3))*16)
#define SWZ(row, chunk) ((row)*64 + ((((chunk) ^ (((row)>>1)&3)) & 3)*16))

#define LF(aa, bb, st, ak, bk) do {                                                 \
    ldsm_x4(aa[0], asb + (uint32_t)(st)*TILE_B + (ak));                             \
    ldsm_x4(aa[1], asb + (uint32_t)(st)*TILE_B + 1024 + (ak));                      \
    ldsm_x4(bb[0], bsb + (uint32_t)(st)*TILE_B + (bk));                             \
    ldsm_x4(bb[1], bsb + (uint32_t)(st)*TILE_B + 1024 + (bk));                      \
    ldsm_x4(bb[2], bsb + (uint32_t)(st)*TILE_B + 2048 + (bk));                      \
    ldsm_x4(bb[3], bsb + (uint32_t)(st)*TILE_B + 3072 + (bk));                      \
} while(0)

#define MMA_SET(aa, bb) do {                                                        \
    _Pragma("unroll")                                                               \
    for (int p = 0; p < 4; p++){                                                    \
        mma_fp16(c[0][2*p+0], aa[0], bb[p][0], bb[p][1]);                           \
        mma_fp16(c[1][2*p+0], aa[1], bb[p][0], bb[p][1]);                           \
        mma_fp16(c[0][2*p+1], aa[0], bb[p][2], bb[p][3]);                           \
        mma_fp16(c[1][2*p+1], aa[1], bb[p][2], bb[p][3]);                           \
    }                                                                               \
} while(0)

#define PREFETCH(ck, st) do {                                                       \
    const size_t ko = (size_t)(ck)*KC;                                              \
    cp_async16(smA + (size_t)(st)*TILE_B + sw0, Agl + ko);                          \
    cp_async16(smA + (size_t)(st)*TILE_B + sw1, Agl + ko + 8);                      \
    cp_async16(smB + (size_t)(st)*TILE_B + sw0, Bgl + ko);                          \
    cp_async16(smB + (size_t)(st)*TILE_B + sw1, Bgl + ko + 8);                      \
    asm volatile("cp.async.commit_group;\n");                                       \
} while(0)

#define WAIT_SYNC() do {                                                            \
    asm volatile("cp.async.wait_group 0;\n");                                       \
    __syncthreads();                                                                \
} while(0)

__global__ void __launch_bounds__(256, 2)
gemm_att_kernel(const float* __restrict__ Wf){
    extern __shared__ char smraw[];
    char* smA = smraw;
    char* smB = smraw + NSTAGE*TILE_B;
    float*  bias_s = (float*)(smraw + EX_OFF);            // [2][128]
    float*  wf_s   = bias_s + 256;
    float*  satt   = wf_s + 128;

    const int tid = threadIdx.x;
    const int bid = blockIdx.x;
    const int m0  = (bid >> 2) * MT;
    const int n0  = (bid & 3)  * NT;
    const int b_first = m0 / P_;

    {
        int j = tid >> 7, c2 = tid & 127;                 // 2 x 128
        int b = b_first + j;
        bias_s[tid] = (b < B_) ? g_att2[(size_t)b*A_ + n0 + c2] : 0.f;
        if (tid < 128){ wf_s[tid] = Wf[n0 + tid]; satt[tid] = 0.f; }
    }

    const int warp = tid >> 5, lane = tid & 31;
    const int wm = warp >> 1, wn = warp & 1;        // 4x2 warp grid; warp tile 32x64
    const int g = lane >> 2, t = lane & 3;

    // ldmatrix per-lane swizzled offsets (within a tile)
    const int a_row = lane & 15;
    const int a_cb  = lane >> 4;                          // 0/1
    const uint32_t aoff0 = SWZ(a_row, a_cb);              // k-step 0
    const uint32_t aoff1 = SWZ(a_row, a_cb + 2);          // k-step 1
    const int b_row = (lane & 7) + ((lane >> 4) & 1) * 8;
    const int b_cb  = (lane >> 3) & 1;
    const uint32_t boff0 = SWZ(b_row, b_cb);
    const uint32_t boff1 = SWZ(b_row, b_cb + 2);

    const uint32_t asb = smem_u32(smA) + (uint32_t)(wm*2048);   // + wm*32 rows
    const uint32_t bsb = smem_u32(smB) + (uint32_t)(wn*4096);   // + wn*64 rows

    // staging: thread covers row tid>>1, chunks {2(tid&1), 2(tid&1)+1}
    const int ld_row = tid >> 1;
    const int ld_c0  = (tid & 1) * 2;
    const uint32_t sw0 = SWZ(ld_row, ld_c0);
    const uint32_t sw1 = SWZ(ld_row, ld_c0 + 1);
    const __half* Agl = g_ench + (size_t)(m0 + ld_row)*E_ + ld_c0*8;
    const __half* Bgl = g_Bth  + (size_t)(n0 + ld_row)*E_ + ld_c0*8;

    float c[2][8][4];
    #pragma unroll
    for (int mi = 0; mi < 2; mi++)
        #pragma unroll
        for (int ni = 0; ni < 8; ni++)
            #pragma unroll
            for (int j = 0; j < 4; j++) c[mi][ni][j] = 0.f;

    uint32_t a0[2][4], b0[4][4], a1[2][4], b1[4][4];

    // ---- prologue: chunks 0..2 resident & visible ----
    PREFETCH(0, 0);
    PREFETCH(1, 1);
    PREFETCH(2, 2);
    WAIT_SYNC();
    LF(a0, b0, 0, aoff0, boff0);                          // chunk 0, k-step 0

    int scur = 0;                                         // stage of chunk kb
    for (int kb = 0; kb < 63; kb += 3){                   // 21 full blocks (chunks 0..62)
        if (kb > 0){
            WAIT_SYNC();
            LF(a0, b0, scur, aoff0, boff0);               // chunk kb, k-step 0
        }
        int s1 = scur+1; if (s1 >= NSTAGE) s1 -= NSTAGE;
        int s2 = s1+1;   if (s2 >= NSTAGE) s2 -= NSTAGE;
        int w3 = s2+1;   if (w3 >= NSTAGE) w3 -= NSTAGE;
        int w4 = w3+1;   if (w4 >= NSTAGE) w4 -= NSTAGE;
        int w5 = w4+1;   if (w5 >= NSTAGE) w5 -= NSTAGE;

        PREFETCH(kb+3, w3);                               // kb+3 <= 63 always

        // chunk kb
        LF(a1, b1, scur, aoff1, boff1);  MMA_SET(a0, b0);
        LF(a0, b0, s1,   aoff0, boff0);  MMA_SET(a1, b1);
        if (kb+4 < NKC) PREFETCH(kb+4, w4);
        // chunk kb+1
        LF(a1, b1, s1,   aoff1, boff1);  MMA_SET(a0, b0);
        LF(a0, b0, s2,   aoff0, boff0);  MMA_SET(a1, b1);
        if (kb+5 < NKC) PREFETCH(kb+5, w5);
        // chunk kb+2 (next chunk's frags deferred past next sync)
        LF(a1, b1, s2,   aoff1, boff1);  MMA_SET(a0, b0);
        MMA_SET(a1, b1);

        scur = w3;
    }
    // tail: chunk 63 (stage 3 == scur)
    WAIT_SYNC();
    LF(a0, b0, scur, aoff0, boff0);
    LF(a1, b1, scur, aoff1, boff1);
    MMA_SET(a0, b0);
    MMA_SET(a1, b1);
    __syncthreads();

    // epilogue: h = relu(acc + bias(b_row, col)); att += h .* Wf
    float attr[2][2] = {{0.f,0.f},{0.f,0.f}};
    #pragma unroll
    for (int ni = 0; ni < 8; ni++){
        const int cl = wn*64 + ni*8 + 2*t;               // local col
        const float w0 = wf_s[cl], w1 = wf_s[cl+1];
        #pragma unroll
        for (int mi = 0; mi < 2; mi++){
            #pragma unroll
            for (int rr = 0; rr < 2; rr++){
                const int rowg = m0 + wm*32 + mi*16 + g + rr*8;
                const int rb   = rowg / P_ - b_first;          // 0 or 1
                const float bv0 = bias_s[rb*128 + cl];
                const float bv1 = bias_s[rb*128 + cl + 1];
                const float h0 = fmaxf(c[mi][ni][rr*2+0] + bv0, 0.f);
                const float h1 = fmaxf(c[mi][ni][rr*2+1] + bv1, 0.f);
                attr[mi][rr] += h0*w0 + h1*w1;
            }
        }
    }
    #pragma unroll
    for (int mi = 0; mi < 2; mi++)
        #pragma unroll
        for (int rr = 0; rr < 2; rr++){
            float v = attr[mi][rr];
            v += __shfl_xor_sync(0xffffffffu, v, 1);
            v += __shfl_xor_sync(0xffffffffu, v, 2);
            if (t == 0) atomicAdd(&satt[wm*32 + mi*16 + g + rr*8], v);
        }
    __syncthreads();
    if (tid < 128) atomicAdd(&g_att[m0 + tid], satt[tid]);
}

// ---------------- kernel 4: fused softmax + awe (one block per batch) ----------------
__global__ void __launch_bounds__(512)
awe_fused(float* __restrict__ alpha_out, float4* __restrict__ out4){
    const int b = blockIdx.x, tid = threadIdx.x;    // 512 threads
    __shared__ float red[512];
    __shared__ float al[P_];

    float v = (tid < P_) ? g_att[b*P_ + tid] : -1e30f;
    red[tid] = v; __syncthreads();
    for (int s = 256; s > 0; s >>= 1){
        if (tid < s) red[tid] = fmaxf(red[tid], red[tid+s]);
        __syncthreads();
    }
    const float mx = red[0]; __syncthreads();
    const float e = (tid < P_) ? expf(v - mx) : 0.f;
    red[tid] = e; __syncthreads();
    for (int s = 256; s > 0; s >>= 1){
        if (tid < s) red[tid] += red[tid+s];
        __syncthreads();
    }
    const float inv = 1.f / red[0];
    if (tid < P_){
        const float a = e * inv;
        alpha_out[b*P_ + tid] = a;
        al[tid] = a;
    }
    __syncthreads();

    float4 acc = make_float4(0.f, 0.f, 0.f, 0.f);
    const uint2* ep = (const uint2*)(g_ench + (size_t)b * P_ * E_) + tid;
    #pragma unroll 4
    for (int p = 0; p < P_; p++){
        const float a = al[p];
        const uint2 u = ep[(size_t)p * (E_/4)];
        const __half2 h0 = *(const __half2*)&u.x;
        const __half2 h1 = *(const __half2*)&u.y;
        acc.x += a * __low2float(h0);  acc.y += a * __high2float(h0);
        acc.z += a * __low2float(h1);  acc.w += a * __high2float(h1);
    }
    out4[(size_t)b * (E_/4) + tid] = acc;
}

// ---------------- launch ----------------
extern "C" void kernel_launch(void* const* d_in, const int* in_sizes, int n_in,
                              void* d_out, int out_size){
    const float* enc  = (const float*)d_in[0];   // (B,P,E)
    const float* dh   = (const float*)d_in[1];   // (1,B,D)
    const float* We_w = (const float*)d_in[2];   // (E,A)
    const float* We_b = (const float*)d_in[3];   // (A)
    const float* Wd_w = (const float*)d_in[4];   // (D,A)
    const float* Wd_b = (const float*)d_in[5];   // (A)
    const float* Wf_w = (const float*)d_in[6];   // (A)
    // d_in[7] = Wf_b: scalar logit shift -> softmax-invariant, outputs don't depend on it.

    float* out       = (float*)d_out;
    float* awe_out   = out;                       // (B,E)
    float* alpha_out = out + (size_t)B_*E_;       // (B,P)

    cudaFuncSetAttribute(gemm_att_kernel, cudaFuncAttributeMaxDynamicSharedMemorySize, SMEM_BYTES);

    prep_bh       <<<dim3(E_/32, A_/32), dim3(32, 8)>>>(We_w);
    prep_ench     <<<(int)((size_t)MTOT*E_/(512*8)), 512>>>(enc);
    att2_kernel   <<<64, 256>>>(dh, Wd_w, Wd_b, We_b);
    gemm_att_kernel<<<(MTOT/MT)*NSPLIT, 256, SMEM_BYTES>>>(Wf_w);   // launch idx 3 -> ncu target
    awe_fused     <<<B_, 512>>>(alpha_out, (float4*)awe_out);
}

// round 13
// speedup vs baseline: 1.4895x; 1.0713x over previous
#include <cuda_runtime.h>
#include <cuda_fp16.h>
#include <cstdint>
#include <cstddef>

#define B_    256
#define P_    196
#define E_    2048
#define A_    512
#define MTOT  (B_*P_)      // 50176

// GEMM tiling: 128x128 tile, 256 threads, 2 CTAs/SM, 6-stage swizzled ring,
// 2-chunk blocks, prefetch distance 4, wait_group 2 (latency-tolerant).
#define MT 128
#define NT 128
#define KC 32
#define NKC (E_/KC)        // 64
#define NSPLIT (A_/NT)     // 4
#define NSTAGE 6
#define TILE_B 8192        // 128 rows x 64B (swizzled, no padding)

// scratch
__device__ float  g_att2[B_*A_];   // dh@Wd + Wd_b + We_b combined bias
__device__ float  g_att [MTOT];    // logits
__device__ __half g_Bth [A_*E_];   // We transposed to [N][K], fp16 (2MB)
__device__ __half g_ench[(size_t)MTOT*E_];  // enc in fp16 (205MB)

// ---------------- helpers ----------------
__device__ __forceinline__ void cp_async16(void* smem_dst, const void* gmem_src){
    unsigned s = (unsigned)__cvta_generic_to_shared(smem_dst);
    asm volatile("cp.async.cg.shared.global [%0], [%1], 16;\n" :: "r"(s), "l"(gmem_src));
}
__device__ __forceinline__ uint32_t packh(float a, float b){
    __half2 h = __floats2half2_rn(a, b);
    return *reinterpret_cast<uint32_t*>(&h);
}
__device__ __forceinline__ void mma_fp16(float c[4], const uint32_t a[4], uint32_t b0, uint32_t b1){
    asm volatile(
        "mma.sync.aligned.m16n8k16.row.col.f32.f16.f16.f32 "
        "{%0,%1,%2,%3}, {%4,%5,%6,%7}, {%8,%9}, {%0,%1,%2,%3};\n"
        : "+f"(c[0]), "+f"(c[1]), "+f"(c[2]), "+f"(c[3])
        : "r"(a[0]), "r"(a[1]), "r"(a[2]), "r"(a[3]), "r"(b0), "r"(b1));
}
__device__ __forceinline__ void ldsm_x4(uint32_t r[4], uint32_t saddr){
    asm volatile("ldmatrix.sync.aligned.m8n8.x4.shared.b16 {%0,%1,%2,%3}, [%4];"
        : "=r"(r[0]), "=r"(r[1]), "=r"(r[2]), "=r"(r[3]) : "r"(saddr));
}
__device__ __forceinline__ uint32_t smem_u32(const void* p){
    return (uint32_t)__cvta_generic_to_shared(p);
}

// ---------------- kernel 0: g_Bth[n][k] = fp16(We[k][n]) ----------------
__global__ void prep_bh(const float* __restrict__ We){
    __shared__ float t[32][33];
    const int k0 = blockIdx.x*32, n0 = blockIdx.y*32;
    const int tx = threadIdx.x, ty = threadIdx.y;   // (32,8)
    #pragma unroll
    for (int i = 0; i < 4; i++)
        t[ty + i*8][tx] = We[(size_t)(k0 + ty + i*8)*A_ + n0 + tx];
    __syncthreads();
    #pragma unroll
    for (int i = 0; i < 4; i++)
        g_Bth[(size_t)(n0 + ty + i*8)*E_ + k0 + tx] = __float2half_rn(t[tx][ty + i*8]);
}

// ---------------- kernel 1: enc -> fp16 (streaming) + zero logits ----------------
__global__ void __launch_bounds__(512)
prep_ench(const float* __restrict__ enc){
    const size_t i = ((size_t)blockIdx.x*512 + threadIdx.x)*8;
    const float4 v0 = *(const float4*)(enc + i);
    const float4 v1 = *(const float4*)(enc + i + 4);
    uint4 w;
    w.x = packh(v0.x, v0.y);  w.y = packh(v0.z, v0.w);
    w.z = packh(v1.x, v1.y);  w.w = packh(v1.z, v1.w);
    *(uint4*)(g_ench + i) = w;
    const int j = blockIdx.x*512 + threadIdx.x;
    if (j < MTOT) g_att[j] = 0.f;
}

// ---------------- kernel 2: att2/bias (64 blocks, 4 batches each) ----------------
__global__ void __launch_bounds__(256)
att2_kernel(const float* __restrict__ dh,  const float* __restrict__ Wd,
            const float* __restrict__ Wdb, const float* __restrict__ Web){
    __shared__ float dh_s[4][512];
    const int tid = threadIdx.x;
    const int bb  = blockIdx.x * 4;
    for (int i = tid; i < 4*512; i += 256)
        dh_s[i >> 9][i & 511] = dh[(size_t)bb*512 + i];
    __syncthreads();

    float acc[4][2];
    {
        const float base0 = Wdb[tid]       + Web[tid];
        const float base1 = Wdb[tid + 256] + Web[tid + 256];
        #pragma unroll
        for (int q = 0; q < 4; q++){ acc[q][0] = base0; acc[q][1] = base1; }
    }
    for (int k = 0; k < 512; k++){
        const float w0 = Wd[(size_t)k*512 + tid];
        const float w1 = Wd[(size_t)k*512 + tid + 256];
        #pragma unroll
        for (int q = 0; q < 4; q++){
            const float d = dh_s[q][k];
            acc[q][0] += d * w0;
            acc[q][1] += d * w1;
        }
    }
    #pragma unroll
    for (int q = 0; q < 4; q++){
        g_att2[(size_t)(bb+q)*512 + tid]       = acc[q][0];
        g_att2[(size_t)(bb+q)*512 + tid + 256] = acc[q][1];
    }
}

// ---------------- kernel 3 (ncu idx 3): fp16 GEMM, swizzled 6-stage ring ----------
// smem: A[6][8KB] | B[6][8KB] | bias[2][128] | wf[128] | satt[128]
#define EX_OFF  (2*NSTAGE*TILE_B)                    // 98304
#define SMEM_BYTES (EX_OFF + (256 + 128 + 128)*4)    // 100352

// swizzled byte offset within a tile: row*64 + ((chunk ^ ((row>>1)&3))*16)
#define SWZ(row, chunk) ((row)*64 + ((((chunk) ^ (((row)>>1)&3)) & 3)*16))

#define LF(aa, bb, st, ak, bk) do {                                                 \
    ldsm_x4(aa[0], asb + (uint32_t)((st)*TILE_B) + (ak));                           \
    ldsm_x4(aa[1], asb + (uint32_t)((st)*TILE_B) + 1024 + (ak));                    \
    ldsm_x4(bb[0], bsb + (uint32_t)((st)*TILE_B) + (bk));                           \
    ldsm_x4(bb[1], bsb + (uint32_t)((st)*TILE_B) + 1024 + (bk));                    \
    ldsm_x4(bb[2], bsb + (uint32_t)((st)*TILE_B) + 2048 + (bk));                    \
    ldsm_x4(bb[3], bsb + (uint32_t)((st)*TILE_B) + 3072 + (bk));                    \
} while(0)

#define MMA_SET(aa, bb) do {                                                        \
    _Pragma("unroll")                                                               \
    for (int p = 0; p < 4; p++){                                                    \
        mma_fp16(c[0][2*p+0], aa[0], bb[p][0], bb[p][1]);                           \
        mma_fp16(c[1][2*p+0], aa[1], bb[p][0], bb[p][1]);                           \
        mma_fp16(c[0][2*p+1], aa[0], bb[p][2], bb[p][3]);                           \
        mma_fp16(c[1][2*p+1], aa[1], bb[p][2], bb[p][3]);                           \
    }                                                                               \
} while(0)

#define PREFETCH(ck, st) do {                                                       \
    const size_t ko = (size_t)(ck)*KC;                                              \
    cp_async16(smA + (size_t)((st)*TILE_B) + sw0, Agl + ko);                        \
    cp_async16(smA + (size_t)((st)*TILE_B) + sw1, Agl + ko + 8);                    \
    cp_async16(smB + (size_t)((st)*TILE_B) + sw0, Bgl + ko);                        \
    cp_async16(smB + (size_t)((st)*TILE_B) + sw1, Bgl + ko + 8);                    \
    asm volatile("cp.async.commit_group;\n");                                       \
} while(0)

// 2-chunk block: stages S0,S0+1; prefetch kb+4 -> SP0, kb+5 -> SP1.
// Top-of-block wait_group 2: chunks kb,kb+1 complete; kb+2,kb+3 stay in flight.
#define BLK(kb, S0, S1, SP0, SP1) do {                                              \
    asm volatile("cp.async.wait_group 2;\n");                                       \
    __syncthreads();                                                                \
    LF(a0, b0, S0, aoff0, boff0);                                                   \
    PREFETCH((kb)+4, SP0);                                                          \
    LF(a1, b1, S0, aoff1, boff1);  MMA_SET(a0, b0);                                 \
    LF(a0, b0, S1, aoff0, boff0);  MMA_SET(a1, b1);                                 \
    PREFETCH((kb)+5, SP1);                                                          \
    LF(a1, b1, S1, aoff1, boff1);  MMA_SET(a0, b0);                                 \
    MMA_SET(a1, b1);                                                                \
} while(0)

// tail block without prefetch; WG = wait_group depth
#define BLK_TAIL(S0, S1, WG) do {                                                   \
    asm volatile("cp.async.wait_group " #WG ";\n");                                 \
    __syncthreads();                                                                \
    LF(a0, b0, S0, aoff0, boff0);                                                   \
    LF(a1, b1, S0, aoff1, boff1);  MMA_SET(a0, b0);                                 \
    LF(a0, b0, S1, aoff0, boff0);  MMA_SET(a1, b1);                                 \
    LF(a1, b1, S1, aoff1, boff1);  MMA_SET(a0, b0);                                 \
    MMA_SET(a1, b1);                                                                \
} while(0)

__global__ void __launch_bounds__(256, 2)
gemm_att_kernel(const float* __restrict__ Wf){
    extern __shared__ char smraw[];
    char* smA = smraw;
    char* smB = smraw + NSTAGE*TILE_B;
    float*  bias_s = (float*)(smraw + EX_OFF);            // [2][128]
    float*  wf_s   = bias_s + 256;
    float*  satt   = wf_s + 128;

    const int tid = threadIdx.x;
    const int bid = blockIdx.x;
    const int m0  = (bid >> 2) * MT;
    const int n0  = (bid & 3)  * NT;
    const int b_first = m0 / P_;

    {
        int j = tid >> 7, c2 = tid & 127;                 // 2 x 128
        int b = b_first + j;
        bias_s[tid] = (b < B_) ? g_att2[(size_t)b*A_ + n0 + c2] : 0.f;
        if (tid < 128){ wf_s[tid] = Wf[n0 + tid]; satt[tid] = 0.f; }
    }

    const int warp = tid >> 5, lane = tid & 31;
    const int wm = warp >> 1, wn = warp & 1;        // 4x2 warp grid; warp tile 32x64
    const int g = lane >> 2, t = lane & 3;

    // ldmatrix per-lane swizzled offsets (within a tile)
    const int a_row = lane & 15;
    const int a_cb  = lane >> 4;                          // 0/1
    const uint32_t aoff0 = SWZ(a_row, a_cb);              // k-step 0
    const uint32_t aoff1 = SWZ(a_row, a_cb + 2);          // k-step 1
    const int b_row = (lane & 7) + ((lane >> 4) & 1) * 8;
    const int b_cb  = (lane >> 3) & 1;
    const uint32_t boff0 = SWZ(b_row, b_cb);
    const uint32_t boff1 = SWZ(b_row, b_cb + 2);

    const uint32_t asb = smem_u32(smA) + (uint32_t)(wm*2048);   // + wm*32 rows
    const uint32_t bsb = smem_u32(smB) + (uint32_t)(wn*4096);   // + wn*64 rows

    // staging: thread covers row tid>>1, chunks {2(tid&1), 2(tid&1)+1}
    const int ld_row = tid >> 1;
    const int ld_c0  = (tid & 1) * 2;
    const uint32_t sw0 = SWZ(ld_row, ld_c0);
    const uint32_t sw1 = SWZ(ld_row, ld_c0 + 1);
    const __half* Agl = g_ench + (size_t)(m0 + ld_row)*E_ + ld_c0*8;
    const __half* Bgl = g_Bth  + (size_t)(n0 + ld_row)*E_ + ld_c0*8;

    float c[2][8][4];
    #pragma unroll
    for (int mi = 0; mi < 2; mi++)
        #pragma unroll
        for (int ni = 0; ni < 8; ni++)
            #pragma unroll
            for (int j = 0; j < 4; j++) c[mi][ni][j] = 0.f;

    uint32_t a0[2][4], b0[4][4], a1[2][4], b1[4][4];

    // ---- prologue: chunks 0..3 in flight (4 commit-groups) ----
    PREFETCH(0, 0);
    PREFETCH(1, 1);
    PREFETCH(2, 2);
    PREFETCH(3, 3);

    // blocks 0..58 (kb step 2), stage period = 3 blocks => fully constant indices
    for (int kb = 0; kb < 60; kb += 6){
        BLK(kb,   0, 1, 4, 5);
        BLK(kb+2, 2, 3, 0, 1);
        BLK(kb+4, 4, 5, 2, 3);
    }
    // tail: chunks 60,61 (stages 0,1; 62,63 still in flight), then 62,63 (stages 2,3)
    BLK_TAIL(0, 1, 2);
    BLK_TAIL(2, 3, 0);
    __syncthreads();

    // epilogue: h = relu(acc + bias(b_row, col)); att += h .* Wf
    float attr[2][2] = {{0.f,0.f},{0.f,0.f}};
    #pragma unroll
    for (int ni = 0; ni < 8; ni++){
        const int cl = wn*64 + ni*8 + 2*t;               // local col
        const float w0 = wf_s[cl], w1 = wf_s[cl+1];
        #pragma unroll
        for (int mi = 0; mi < 2; mi++){
            #pragma unroll
            for (int rr = 0; rr < 2; rr++){
                const int rowg = m0 + wm*32 + mi*16 + g + rr*8;
                const int rb   = rowg / P_ - b_first;          // 0 or 1
                const float bv0 = bias_s[rb*128 + cl];
                const float bv1 = bias_s[rb*128 + cl + 1];
                const float h0 = fmaxf(c[mi][ni][rr*2+0] + bv0, 0.f);
                const float h1 = fmaxf(c[mi][ni][rr*2+1] + bv1, 0.f);
                attr[mi][rr] += h0*w0 + h1*w1;
            }
        }
    }
    #pragma unroll
    for (int mi = 0; mi < 2; mi++)
        #pragma unroll
        for (int rr = 0; rr < 2; rr++){
            float v = attr[mi][rr];
            v += __shfl_xor_sync(0xffffffffu, v, 1);
            v += __shfl_xor_sync(0xffffffffu, v, 2);
            if (t == 0) atomicAdd(&satt[wm*32 + mi*16 + g + rr*8], v);
        }
    __syncthreads();
    if (tid < 128) atomicAdd(&g_att[m0 + tid], satt[tid]);
}

// ---------------- kernel 4: fused softmax + awe (one block per batch) ----------------
__global__ void __launch_bounds__(512)
awe_fused(float* __restrict__ alpha_out, float4* __restrict__ out4){
    const int b = blockIdx.x, tid = threadIdx.x;    // 512 threads
    __shared__ float red[512];
    __shared__ float al[P_];

    float v = (tid < P_) ? g_att[b*P_ + tid] : -1e30f;
    red[tid] = v; __syncthreads();
    for (int s = 256; s > 0; s >>= 1){
        if (tid < s) red[tid] = fmaxf(red[tid], red[tid+s]);
        __syncthreads();
    }
    const float mx = red[0]; __syncthreads();
    const float e = (tid < P_) ? expf(v - mx) : 0.f;
    red[tid] = e; __syncthreads();
    for (int s = 256; s > 0; s >>= 1){
        if (tid < s) red[tid] += red[tid+s];
        __syncthreads();
    }
    const float inv = 1.f / red[0];
    if (tid < P_){
        const float a = e * inv;
        alpha_out[b*P_ + tid] = a;
        al[tid] = a;
    }
    __syncthreads();

    float4 acc = make_float4(0.f, 0.f, 0.f, 0.f);
    const uint2* ep = (const uint2*)(g_ench + (size_t)b * P_ * E_) + tid;
    #pragma unroll 4
    for (int p = 0; p < P_; p++){
        const float a = al[p];
        const uint2 u = ep[(size_t)p * (E_/4)];
        const __half2 h0 = *(const __half2*)&u.x;
        const __half2 h1 = *(const __half2*)&u.y;
        acc.x += a * __low2float(h0);  acc.y += a * __high2float(h0);
        acc.z += a * __low2float(h1);  acc.w += a * __high2float(h1);
    }
    out4[(size_t)b * (E_/4) + tid] = acc;
}

// ---------------- launch ----------------
extern "C" void kernel_launch(void* const* d_in, const int* in_sizes, int n_in,
                              void* d_out, int out_size){
    const float* enc  = (const float*)d_in[0];   // (B,P,E)
    const float* dh   = (const float*)d_in[1];   // (1,B,D)
    const float* We_w = (const float*)d_in[2];   // (E,A)
    const float* We_b = (const float*)d_in[3];   // (A)
    const float* Wd_w = (const float*)d_in[4];   // (D,A)
    const float* Wd_b = (const float*)d_in[5];   // (A)
    const float* Wf_w = (const float*)d_in[6];   // (A)
    // d_in[7] = Wf_b: scalar logit shift -> softmax-invariant, outputs don't depend on it.

    float* out       = (float*)d_out;
    float* awe_out   = out;                       // (B,E)
    float* alpha_out = out + (size_t)B_*E_;       // (B,P)

    cudaFuncSetAttribute(gemm_att_kernel, cudaFuncAttributeMaxDynamicSharedMemorySize, SMEM_BYTES);

    prep_bh       <<<dim3(E_/32, A_/32), dim3(32, 8)>>>(We_w);
    prep_ench     <<<(int)((size_t)MTOT*E_/(512*8)), 512>>>(enc);
    att2_kernel   <<<64, 256>>>(dh, Wd_w, Wd_b, We_b);
    gemm_att_kernel<<<(MTOT/MT)*NSPLIT, 256, SMEM_BYTES>>>(Wf_w);   // launch idx 3 -> ncu target
    awe_fused     <<<B_, 512>>>(alpha_out, (float4*)awe_out);
}